// round 1
// baseline (speedup 1.0000x reference)
#include <cuda_runtime.h>
#include <math.h>

#define D_MODEL 1024
#define D_FF    4096
#define NE      8
#define MAX_T   2048

// ---------------- scratch (static __device__, no allocations) ----------------
__device__ int   g_counts[NE];
__device__ int   g_offsets[NE];
__device__ int   g_tok[NE * MAX_T];
__device__ float g_w[NE * MAX_T];
__device__ float g_H[(size_t)(2 * MAX_T) * D_FF];   // 64 MB compact hidden acts

// ---------------- init: zero counts + output ----------------
__global__ void init_kernel(float* __restrict__ out, int n_out) {
    int i = blockIdx.x * blockDim.x + threadIdx.x;
    if (i < NE) g_counts[i] = 0;
    int stride = gridDim.x * blockDim.x;
    for (int j = i; j < n_out; j += stride) out[j] = 0.0f;
}

// ---------------- router: logits -> softmax -> top2 -> renorm -> bucket ----------------
__global__ void router_kernel(const float* __restrict__ x,
                              const float* __restrict__ Wr,
                              const float* __restrict__ br) {
    const int t = blockIdx.x;
    const int tid = threadIdx.x;  // 128 threads
    float acc[NE];
#pragma unroll
    for (int e = 0; e < NE; e++) acc[e] = 0.0f;
    const float* xr = x + (size_t)t * D_MODEL;
    for (int d = tid; d < D_MODEL; d += 128) {
        float xv = xr[d];
        const float4* w4 = reinterpret_cast<const float4*>(Wr + (size_t)d * NE);
        float4 a = w4[0], b = w4[1];
        acc[0] += xv * a.x; acc[1] += xv * a.y;
        acc[2] += xv * a.z; acc[3] += xv * a.w;
        acc[4] += xv * b.x; acc[5] += xv * b.y;
        acc[6] += xv * b.z; acc[7] += xv * b.w;
    }
    __shared__ float red[128][NE];
#pragma unroll
    for (int e = 0; e < NE; e++) red[tid][e] = acc[e];
    __syncthreads();
    for (int s = 64; s > 0; s >>= 1) {
        if (tid < s) {
#pragma unroll
            for (int e = 0; e < NE; e++) red[tid][e] += red[tid + s][e];
        }
        __syncthreads();
    }
    if (tid == 0) {
        float l[NE];
#pragma unroll
        for (int e = 0; e < NE; e++) l[e] = red[0][e] + br[e];
        int i0 = 0;
#pragma unroll
        for (int e = 1; e < NE; e++) if (l[e] > l[i0]) i0 = e;
        int i1 = (i0 == 0) ? 1 : 0;
#pragma unroll
        for (int e = 0; e < NE; e++) if (e != i0 && l[e] > l[i1]) i1 = e;
        // renormalized top-2 softmax weights (global softmax denom cancels)
        float m  = fmaxf(l[i0], l[i1]);
        float e0 = expf(l[i0] - m), e1 = expf(l[i1] - m);
        float inv = 1.0f / (e0 + e1);
        int p0 = atomicAdd(&g_counts[i0], 1);
        g_tok[i0 * MAX_T + p0] = t;  g_w[i0 * MAX_T + p0] = e0 * inv;
        int p1 = atomicAdd(&g_counts[i1], 1);
        g_tok[i1 * MAX_T + p1] = t;  g_w[i1 * MAX_T + p1] = e1 * inv;
    }
}

// ---------------- offsets: 8-element exclusive scan ----------------
__global__ void offsets_kernel() {
    int off = 0;
#pragma unroll
    for (int e = 0; e < NE; e++) { g_offsets[e] = off; off += g_counts[e]; }
}

// ---------------- GEMM1: H = silu(Xg @ Wg + bg) * (Xg @ Wu + bu), gathered rows ----------------
// block tile 128(M) x 64(N), BK=16, 256 threads, per-thread 8x4 for gate and up
__global__ __launch_bounds__(256) void gemm1_kernel(
    const float* __restrict__ x,
    const float* __restrict__ Wg, const float* __restrict__ bg,
    const float* __restrict__ Wu, const float* __restrict__ bu) {
    const int e   = blockIdx.z;
    const int cnt = g_counts[e];
    const int m0  = blockIdx.y * 128;
    if (m0 >= cnt) return;
    const int n0  = blockIdx.x * 64;
    const int tid = threadIdx.x;
    const int tx  = tid & 15;   // 16 col groups * 4 cols
    const int ty  = tid >> 4;   // 16 row groups * 8 rows

    __shared__ float As[16][128];
    __shared__ float Bgs[16][64];
    __shared__ float Bus[16][64];

    const float* Wge = Wg + (size_t)e * D_MODEL * D_FF;
    const float* Wue = Wu + (size_t)e * D_MODEL * D_FF;

    // A loads: 128x16 = 512 float4, 2 per thread. row fixed across k-iters.
    const int ar  = tid >> 2;          // 0..63
    const int akq = (tid & 3) * 4;     // k sub-offset 0,4,8,12
    const float* aptr[2];
#pragma unroll
    for (int i = 0; i < 2; i++) {
        int gr = m0 + ar + i * 64;
        aptr[i] = (gr < cnt) ? (x + (size_t)g_tok[e * MAX_T + gr] * D_MODEL) : nullptr;
    }
    // B loads: 16x64 per matrix = 256 float4, 1 per thread per matrix
    const int bk = tid >> 4;
    const int bn = (tid & 15) * 4;

    float accg[8][4], accu[8][4];
#pragma unroll
    for (int r = 0; r < 8; r++)
#pragma unroll
        for (int c = 0; c < 4; c++) { accg[r][c] = 0.f; accu[r][c] = 0.f; }

    for (int k0 = 0; k0 < D_MODEL; k0 += 16) {
#pragma unroll
        for (int i = 0; i < 2; i++) {
            float4 v = make_float4(0.f, 0.f, 0.f, 0.f);
            if (aptr[i]) v = *reinterpret_cast<const float4*>(aptr[i] + k0 + akq);
            int r = ar + i * 64;
            As[akq + 0][r] = v.x; As[akq + 1][r] = v.y;
            As[akq + 2][r] = v.z; As[akq + 3][r] = v.w;
        }
        *reinterpret_cast<float4*>(&Bgs[bk][bn]) =
            *reinterpret_cast<const float4*>(Wge + (size_t)(k0 + bk) * D_FF + n0 + bn);
        *reinterpret_cast<float4*>(&Bus[bk][bn]) =
            *reinterpret_cast<const float4*>(Wue + (size_t)(k0 + bk) * D_FF + n0 + bn);
        __syncthreads();
#pragma unroll
        for (int k = 0; k < 16; k++) {
            float4 a0 = *reinterpret_cast<const float4*>(&As[k][ty * 8]);
            float4 a1 = *reinterpret_cast<const float4*>(&As[k][ty * 8 + 4]);
            float a[8] = {a0.x, a0.y, a0.z, a0.w, a1.x, a1.y, a1.z, a1.w};
            float4 bgv = *reinterpret_cast<const float4*>(&Bgs[k][tx * 4]);
            float4 buv = *reinterpret_cast<const float4*>(&Bus[k][tx * 4]);
            float bg4[4] = {bgv.x, bgv.y, bgv.z, bgv.w};
            float bu4[4] = {buv.x, buv.y, buv.z, buv.w};
#pragma unroll
            for (int r = 0; r < 8; r++)
#pragma unroll
                for (int c = 0; c < 4; c++) {
                    accg[r][c] = fmaf(a[r], bg4[c], accg[r][c]);
                    accu[r][c] = fmaf(a[r], bu4[c], accu[r][c]);
                }
        }
        __syncthreads();
    }
    const int hbase = g_offsets[e];
#pragma unroll
    for (int r = 0; r < 8; r++) {
        int gr = m0 + ty * 8 + r;
        if (gr >= cnt) continue;
        float* hrow = g_H + (size_t)(hbase + gr) * D_FF;
        int n = n0 + tx * 4;
        float4 bgb = *reinterpret_cast<const float4*>(bg + (size_t)e * D_FF + n);
        float4 bub = *reinterpret_cast<const float4*>(bu + (size_t)e * D_FF + n);
        float gb[4] = {bgb.x, bgb.y, bgb.z, bgb.w};
        float ub[4] = {bub.x, bub.y, bub.z, bub.w};
        float4 h;
        float hv[4];
#pragma unroll
        for (int c = 0; c < 4; c++) {
            float g = accg[r][c] + gb[c];
            float u = accu[r][c] + ub[c];
            float s = g / (1.0f + expf(-g));   // silu
            hv[c] = s * u;
        }
        h.x = hv[0]; h.y = hv[1]; h.z = hv[2]; h.w = hv[3];
        *reinterpret_cast<float4*>(hrow + n) = h;
    }
}

// ---------------- GEMM2: out[tok] += w * (H @ Wd + bd), scatter ----------------
// block tile 128(M) x 128(N), BK=16, 256 threads, per-thread 8x8
__global__ __launch_bounds__(256) void gemm2_kernel(
    const float* __restrict__ Wd, const float* __restrict__ bd,
    float* __restrict__ out) {
    const int e   = blockIdx.z;
    const int cnt = g_counts[e];
    const int m0  = blockIdx.y * 128;
    if (m0 >= cnt) return;
    const int n0  = blockIdx.x * 128;
    const int tid = threadIdx.x;
    const int tx  = tid & 15;   // 16 col groups * 8 cols
    const int ty  = tid >> 4;   // 16 row groups * 8 rows

    __shared__ float As[16][128];
    __shared__ float Bs[16][128];

    const float* Wde  = Wd + (size_t)e * D_FF * D_MODEL;
    const int    hbase = g_offsets[e];

    const int ar  = tid >> 2;
    const int akq = (tid & 3) * 4;
    const float* aptr[2];
#pragma unroll
    for (int i = 0; i < 2; i++) {
        int gr = m0 + ar + i * 64;
        aptr[i] = (gr < cnt) ? (g_H + (size_t)(hbase + gr) * D_FF) : nullptr;
    }

    float acc[8][8];
#pragma unroll
    for (int r = 0; r < 8; r++)
#pragma unroll
        for (int c = 0; c < 8; c++) acc[r][c] = 0.f;

    for (int k0 = 0; k0 < D_FF; k0 += 16) {
#pragma unroll
        for (int i = 0; i < 2; i++) {
            float4 v = make_float4(0.f, 0.f, 0.f, 0.f);
            if (aptr[i]) v = *reinterpret_cast<const float4*>(aptr[i] + k0 + akq);
            int r = ar + i * 64;
            As[akq + 0][r] = v.x; As[akq + 1][r] = v.y;
            As[akq + 2][r] = v.z; As[akq + 3][r] = v.w;
        }
#pragma unroll
        for (int i = 0; i < 2; i++) {
            int li = tid + i * 256;           // 0..511
            int k  = li >> 5;                 // 0..15
            int nq = (li & 31) * 4;           // 0..124
            *reinterpret_cast<float4*>(&Bs[k][nq]) =
                *reinterpret_cast<const float4*>(Wde + (size_t)(k0 + k) * D_MODEL + n0 + nq);
        }
        __syncthreads();
#pragma unroll
        for (int k = 0; k < 16; k++) {
            float4 a0 = *reinterpret_cast<const float4*>(&As[k][ty * 8]);
            float4 a1 = *reinterpret_cast<const float4*>(&As[k][ty * 8 + 4]);
            float a[8] = {a0.x, a0.y, a0.z, a0.w, a1.x, a1.y, a1.z, a1.w};
            float4 b0 = *reinterpret_cast<const float4*>(&Bs[k][tx * 8]);
            float4 b1 = *reinterpret_cast<const float4*>(&Bs[k][tx * 8 + 4]);
            float b[8] = {b0.x, b0.y, b0.z, b0.w, b1.x, b1.y, b1.z, b1.w};
#pragma unroll
            for (int r = 0; r < 8; r++)
#pragma unroll
                for (int c = 0; c < 8; c++)
                    acc[r][c] = fmaf(a[r], b[c], acc[r][c]);
        }
        __syncthreads();
    }
#pragma unroll
    for (int r = 0; r < 8; r++) {
        int gr = m0 + ty * 8 + r;
        if (gr >= cnt) continue;
        int   tok = g_tok[e * MAX_T + gr];
        float w   = g_w[e * MAX_T + gr];
        float* orow = out + (size_t)tok * D_MODEL;
#pragma unroll
        for (int c = 0; c < 8; c++) {
            int n = n0 + tx * 8 + c;
            float v = w * (acc[r][c] + bd[(size_t)e * D_MODEL + n]);
            atomicAdd(&orow[n], v);   // exactly 2 adds per element -> deterministic
        }
    }
}

// ---------------- launch ----------------
extern "C" void kernel_launch(void* const* d_in, const int* in_sizes, int n_in,
                              void* d_out, int out_size) {
    const float* x  = (const float*)d_in[0];
    const float* Wr = (const float*)d_in[1];
    const float* br = (const float*)d_in[2];
    const float* Wg = (const float*)d_in[3];
    const float* bg = (const float*)d_in[4];
    const float* Wu = (const float*)d_in[5];
    const float* bu = (const float*)d_in[6];
    const float* Wd = (const float*)d_in[7];
    const float* bd = (const float*)d_in[8];
    float* out = (float*)d_out;

    int T = in_sizes[0] / D_MODEL;   // 2048

    init_kernel<<<256, 256>>>(out, out_size);
    router_kernel<<<T, 128>>>(x, Wr, br);
    offsets_kernel<<<1, 1>>>();

    dim3 g1(D_FF / 64, (MAX_T + 127) / 128, NE);
    gemm1_kernel<<<g1, 256>>>(x, Wg, bg, Wu, bu);

    dim3 g2(D_MODEL / 128, (MAX_T + 127) / 128, NE);
    gemm2_kernel<<<g2, 256>>>(Wd, bd, out);
}

// round 6
// speedup vs baseline: 2.8589x; 2.8589x over previous
#include <cuda_runtime.h>
#include <math.h>

#define D_MODEL 1024
#define D_FF    4096
#define NE      8
#define MAX_T   2048
#define BK      32

// ---------------- scratch (static __device__, no allocations) ----------------
__device__ int   g_counts[NE];
__device__ int   g_offsets[NE];
__device__ int   g_tok[NE * MAX_T];
__device__ float g_w[NE * MAX_T];
__device__ float g_H[(size_t)(2 * MAX_T) * D_FF];   // 64 MB compact hidden acts

// ---------------- helpers ----------------
__device__ __forceinline__ unsigned smem_u32(const void* p) {
    unsigned a;
    asm("{ .reg .u64 t; cvta.to.shared.u64 t, %1; cvt.u32.u64 %0, t; }" : "=r"(a) : "l"(p));
    return a;
}
// store 4 floats as tf32 (round-to-nearest) to shared
__device__ __forceinline__ void sts_tf32x4(unsigned addr, float4 v) {
    asm volatile("{ .reg .b32 a,b,c,d;\n\t"
                 "cvt.rna.tf32.f32 a, %1; cvt.rna.tf32.f32 b, %2;\n\t"
                 "cvt.rna.tf32.f32 c, %3; cvt.rna.tf32.f32 d, %4;\n\t"
                 "st.shared.v4.b32 [%0], {a,b,c,d}; }"
                 :: "r"(addr), "f"(v.x), "f"(v.y), "f"(v.z), "f"(v.w) : "memory");
}
__device__ __forceinline__ void ldm_x4(unsigned& r0, unsigned& r1, unsigned& r2, unsigned& r3,
                                       unsigned addr) {
    asm volatile("ldmatrix.sync.aligned.m8n8.x4.shared.b16 {%0,%1,%2,%3}, [%4];"
                 : "=r"(r0), "=r"(r1), "=r"(r2), "=r"(r3) : "r"(addr));
}
__device__ __forceinline__ void mma_frag(float* d, const unsigned* a, const unsigned* b) {
    asm volatile("mma.sync.aligned.m16n8k8.row.col.f32.tf32.tf32.f32 "
                 "{%0,%1,%2,%3}, {%4,%5,%6,%7}, {%8,%9}, {%0,%1,%2,%3};"
                 : "+f"(d[0]), "+f"(d[1]), "+f"(d[2]), "+f"(d[3])
                 : "r"(a[0]), "r"(a[1]), "r"(a[2]), "r"(a[3]), "r"(b[0]), "r"(b[1]));
}
#define SWZ(o) ((o) ^ (((o) >> 3) & 0x70))

// ---------------- init: zero counts + output ----------------
__global__ void init_kernel(float* __restrict__ out, int n_out) {
    int i = blockIdx.x * blockDim.x + threadIdx.x;
    if (i < NE) g_counts[i] = 0;
    int stride = gridDim.x * blockDim.x;
    for (int j = i; j < n_out; j += stride) out[j] = 0.0f;
}

// ---------------- router (validated) ----------------
__global__ void router_kernel(const float* __restrict__ x,
                              const float* __restrict__ Wr,
                              const float* __restrict__ br) {
    const int t = blockIdx.x;
    const int tid = threadIdx.x;  // 128 threads
    float acc[NE];
#pragma unroll
    for (int e = 0; e < NE; e++) acc[e] = 0.0f;
    const float* xr = x + (size_t)t * D_MODEL;
    for (int d = tid; d < D_MODEL; d += 128) {
        float xv = xr[d];
        const float4* w4 = reinterpret_cast<const float4*>(Wr + (size_t)d * NE);
        float4 a = w4[0], b = w4[1];
        acc[0] += xv * a.x; acc[1] += xv * a.y;
        acc[2] += xv * a.z; acc[3] += xv * a.w;
        acc[4] += xv * b.x; acc[5] += xv * b.y;
        acc[6] += xv * b.z; acc[7] += xv * b.w;
    }
    __shared__ float red[128][NE];
#pragma unroll
    for (int e = 0; e < NE; e++) red[tid][e] = acc[e];
    __syncthreads();
    for (int s = 64; s > 0; s >>= 1) {
        if (tid < s) {
#pragma unroll
            for (int e = 0; e < NE; e++) red[tid][e] += red[tid + s][e];
        }
        __syncthreads();
    }
    if (tid == 0) {
        float l[NE];
#pragma unroll
        for (int e = 0; e < NE; e++) l[e] = red[0][e] + br[e];
        int i0 = 0;
#pragma unroll
        for (int e = 1; e < NE; e++) if (l[e] > l[i0]) i0 = e;
        int i1 = (i0 == 0) ? 1 : 0;
#pragma unroll
        for (int e = 0; e < NE; e++) if (e != i0 && l[e] > l[i1]) i1 = e;
        float m  = fmaxf(l[i0], l[i1]);
        float e0 = expf(l[i0] - m), e1 = expf(l[i1] - m);
        float inv = 1.0f / (e0 + e1);
        int p0 = atomicAdd(&g_counts[i0], 1);
        g_tok[i0 * MAX_T + p0] = t;  g_w[i0 * MAX_T + p0] = e0 * inv;
        int p1 = atomicAdd(&g_counts[i1], 1);
        g_tok[i1 * MAX_T + p1] = t;  g_w[i1 * MAX_T + p1] = e1 * inv;
    }
}

__global__ void offsets_kernel() {
    int off = 0;
#pragma unroll
    for (int e = 0; e < NE; e++) { g_offsets[e] = off; off += g_counts[e]; }
}

// =====================================================================
// GEMM1: 128 tokens x 64 f per CTA, gate+up fused (B tile = 128 smem rows:
// rows [q*32, q*32+16) = gate f, [q*32+16, q*32+32) = up f). K=1024.
// 8 warps (2m x 4n), warp tile 64x32 via mma.sync m16n8k8 tf32.
// =====================================================================
__global__ __launch_bounds__(256) void gemm1_tc(
    const float* __restrict__ x,
    const float* __restrict__ Wg, const float* __restrict__ bg,
    const float* __restrict__ Wu, const float* __restrict__ bu) {
    const int e   = blockIdx.z;
    const int cnt = g_counts[e];
    const int m0  = blockIdx.x * 128;
    if (m0 >= cnt) return;
    const int f0  = blockIdx.y * 64;

    extern __shared__ char dsm[];
    const unsigned sbase = (smem_u32(dsm) + 1023u) & ~1023u;

    const int tid = threadIdx.x, wid = tid >> 5, lane = tid & 31;
    const int wm = wid & 1, wn = wid >> 1;

    // A gather
    const int ar = tid >> 1, ah = tid & 1;
    const float* ap = nullptr;
    if (m0 + ar < cnt) ap = x + (size_t)g_tok[e * MAX_T + m0 + ar] * D_MODEL + ah * 16;
    const float* wgp = Wg + (size_t)e * D_MODEL * D_FF + f0;
    const float* wup = Wu + (size_t)e * D_MODEL * D_FF + f0;
    const int kr = wid * 4;

    const int f_j0 = lane, f_j1 = lane + 32;
    const int rg0 = ((f_j0 >> 4) << 5) + (f_j0 & 15);
    const int rg1 = ((f_j1 >> 4) << 5) + (f_j1 & 15);

    // ldmatrix lane constants
    const unsigned xmask = (unsigned)((lane & 7) << 4);
    const int mrow = ((lane >> 3) & 1) * 8 + (lane & 7);
    const unsigned akh = (unsigned)((lane >> 4) * 16);
    const int nrow = ((lane >> 4) * 8) + (lane & 7);
    const unsigned bkh = (unsigned)(((lane >> 3) & 1) * 16);

    float d[4][4][4];
#pragma unroll
    for (int i = 0; i < 4; i++)
#pragma unroll
        for (int j = 0; j < 4; j++)
#pragma unroll
            for (int q = 0; q < 4; q++) d[i][j][q] = 0.f;

    float4 pa[4];
    float  pb[4][4];

    auto ldg = [&](int k0) {
#pragma unroll
        for (int q = 0; q < 4; q++) {
            pa[q] = make_float4(0.f, 0.f, 0.f, 0.f);
            if (ap) pa[q] = *reinterpret_cast<const float4*>(ap + k0 + q * 4);
        }
#pragma unroll
        for (int i = 0; i < 4; i++) {
            size_t ro = (size_t)(k0 + kr + i) * D_FF;
            pb[0][i] = wgp[ro + f_j0];
            pb[1][i] = wgp[ro + f_j1];
            pb[2][i] = wup[ro + f_j0];
            pb[3][i] = wup[ro + f_j1];
        }
    };
    auto sts = [&](int buf) {
        unsigned Ab = sbase + (unsigned)buf * 32768u;
        unsigned Bb = Ab + 16384u;
#pragma unroll
        for (int q = 0; q < 4; q++)
            sts_tf32x4(Ab + SWZ((unsigned)(ar * 128 + ah * 64 + q * 16)), pa[q]);
        const int rows[4] = { rg0, rg1, rg0 + 16, rg1 + 16 };
#pragma unroll
        for (int g = 0; g < 4; g++)
            sts_tf32x4(Bb + SWZ((unsigned)(rows[g] * 128 + kr * 4)),
                       make_float4(pb[g][0], pb[g][1], pb[g][2], pb[g][3]));
    };
    auto comp = [&](int buf) {
        unsigned Ab = sbase + (unsigned)buf * 32768u;
        unsigned Bb = Ab + 16384u;
#pragma unroll
        for (int ks = 0; ks < 4; ks++) {
            unsigned a[4][4];
#pragma unroll
            for (int mf = 0; mf < 4; mf++)
                ldm_x4(a[mf][0], a[mf][1], a[mf][2], a[mf][3],
                       Ab + (unsigned)((wm * 64 + mf * 16 + mrow) * 128) +
                       ((akh + ks * 32) ^ xmask));
            unsigned b[4][2];
#pragma unroll
            for (int nf2 = 0; nf2 < 2; nf2++)
                ldm_x4(b[2 * nf2][0], b[2 * nf2][1], b[2 * nf2 + 1][0], b[2 * nf2 + 1][1],
                       Bb + (unsigned)((wn * 32 + nf2 * 16 + nrow) * 128) +
                       ((bkh + ks * 32) ^ xmask));
#pragma unroll
            for (int mf = 0; mf < 4; mf++)
#pragma unroll
                for (int nf = 0; nf < 4; nf++)
                    mma_frag(d[mf][nf], a[mf], b[nf]);
        }
    };

    ldg(0); sts(0); __syncthreads();
    const int NST = D_MODEL / BK;   // 32
    for (int s = 0; s < NST; s++) {
        if (s + 1 < NST) ldg((s + 1) * BK);
        comp(s & 1);
        __syncthreads();
        if (s + 1 < NST) { sts((s + 1) & 1); __syncthreads(); }
    }

    // epilogue: h = silu(g+bg)*(u+bu) -> g_H  (nf 0,1 = gate; 2,3 = up, same f)
    const int hb = g_offsets[e];
    const float* bge = bg + (size_t)e * D_FF;
    const float* bue = bu + (size_t)e * D_FF;
    const int mbase = m0 + wm * 64 + (lane >> 2);
    const int cb = (lane & 3) * 2;
#pragma unroll
    for (int mf = 0; mf < 4; mf++) {
#pragma unroll
        for (int rs = 0; rs < 2; rs++) {
            int gr = mbase + mf * 16 + rs * 8;
            if (gr >= cnt) continue;
            float* hrow = g_H + (size_t)(hb + gr) * D_FF;
#pragma unroll
            for (int nf = 0; nf < 2; nf++) {
                int f = f0 + wn * 16 + nf * 8 + cb;
                float g0 = d[mf][nf][rs * 2 + 0] + bge[f];
                float g1 = d[mf][nf][rs * 2 + 1] + bge[f + 1];
                float u0 = d[mf][nf + 2][rs * 2 + 0] + bue[f];
                float u1 = d[mf][nf + 2][rs * 2 + 1] + bue[f + 1];
                float h0 = (g0 / (1.0f + expf(-g0))) * u0;
                float h1 = (g1 / (1.0f + expf(-g1))) * u1;
                *reinterpret_cast<float2*>(hrow + f) = make_float2(h0, h1);
            }
        }
    }
}

// =====================================================================
// GEMM2: out[tok] += w * (H @ Wd + bd). CTA 128 x 128, K=4096. Same engine.
// =====================================================================
__global__ __launch_bounds__(256) void gemm2_tc(
    const float* __restrict__ Wd, const float* __restrict__ bd,
    float* __restrict__ out) {
    const int e   = blockIdx.z;
    const int cnt = g_counts[e];
    const int m0  = blockIdx.x * 128;
    if (m0 >= cnt) return;
    const int n0  = blockIdx.y * 128;

    extern __shared__ char dsm[];
    const unsigned sbase = (smem_u32(dsm) + 1023u) & ~1023u;

    const int tid = threadIdx.x, wid = tid >> 5, lane = tid & 31;
    const int wm = wid & 1, wn = wid >> 1;

    const int hb = g_offsets[e];
    const int ar = tid >> 1, ah = tid & 1;
    const float* ap = nullptr;
    if (m0 + ar < cnt) ap = g_H + (size_t)(hb + m0 + ar) * D_FF + ah * 16;
    const float* wdp = Wd + (size_t)e * D_FF * D_MODEL + n0;
    const int kr = wid * 4;

    const unsigned xmask = (unsigned)((lane & 7) << 4);
    const int mrow = ((lane >> 3) & 1) * 8 + (lane & 7);
    const unsigned akh = (unsigned)((lane >> 4) * 16);
    const int nrow = ((lane >> 4) * 8) + (lane & 7);
    const unsigned bkh = (unsigned)(((lane >> 3) & 1) * 16);

    float d[4][4][4];
#pragma unroll
    for (int i = 0; i < 4; i++)
#pragma unroll
        for (int j = 0; j < 4; j++)
#pragma unroll
            for (int q = 0; q < 4; q++) d[i][j][q] = 0.f;

    float4 pa[4];
    float  pb[4][4];

    auto ldg = [&](int k0) {
#pragma unroll
        for (int q = 0; q < 4; q++) {
            pa[q] = make_float4(0.f, 0.f, 0.f, 0.f);
            if (ap) pa[q] = *reinterpret_cast<const float4*>(ap + k0 + q * 4);
        }
#pragma unroll
        for (int i = 0; i < 4; i++) {
            size_t ro = (size_t)(k0 + kr + i) * D_MODEL;
#pragma unroll
            for (int j = 0; j < 4; j++)
                pb[j][i] = wdp[ro + lane + 32 * j];
        }
    };
    auto sts = [&](int buf) {
        unsigned Ab = sbase + (unsigned)buf * 32768u;
        unsigned Bb = Ab + 16384u;
#pragma unroll
        for (int q = 0; q < 4; q++)
            sts_tf32x4(Ab + SWZ((unsigned)(ar * 128 + ah * 64 + q * 16)), pa[q]);
#pragma unroll
        for (int j = 0; j < 4; j++)
            sts_tf32x4(Bb + SWZ((unsigned)((lane + 32 * j) * 128 + kr * 4)),
                       make_float4(pb[j][0], pb[j][1], pb[j][2], pb[j][3]));
    };
    auto comp = [&](int buf) {
        unsigned Ab = sbase + (unsigned)buf * 32768u;
        unsigned Bb = Ab + 16384u;
#pragma unroll
        for (int ks = 0; ks < 4; ks++) {
            unsigned a[4][4];
#pragma unroll
            for (int mf = 0; mf < 4; mf++)
                ldm_x4(a[mf][0], a[mf][1], a[mf][2], a[mf][3],
                       Ab + (unsigned)((wm * 64 + mf * 16 + mrow) * 128) +
                       ((akh + ks * 32) ^ xmask));
            unsigned b[4][2];
#pragma unroll
            for (int nf2 = 0; nf2 < 2; nf2++)
                ldm_x4(b[2 * nf2][0], b[2 * nf2][1], b[2 * nf2 + 1][0], b[2 * nf2 + 1][1],
                       Bb + (unsigned)((wn * 32 + nf2 * 16 + nrow) * 128) +
                       ((bkh + ks * 32) ^ xmask));
#pragma unroll
            for (int mf = 0; mf < 4; mf++)
#pragma unroll
                for (int nf = 0; nf < 4; nf++)
                    mma_frag(d[mf][nf], a[mf], b[nf]);
        }
    };

    ldg(0); sts(0); __syncthreads();
    const int NST = D_FF / BK;   // 128
    for (int s = 0; s < NST; s++) {
        if (s + 1 < NST) ldg((s + 1) * BK);
        comp(s & 1);
        __syncthreads();
        if (s + 1 < NST) { sts((s + 1) & 1); __syncthreads(); }
    }

    // epilogue: out[tok, n] += w * (acc + bd)
    const float* bde = bd + (size_t)e * D_MODEL;
    const int mbase = m0 + wm * 64 + (lane >> 2);
    const int cb = (lane & 3) * 2;
#pragma unroll
    for (int mf = 0; mf < 4; mf++) {
#pragma unroll
        for (int rs = 0; rs < 2; rs++) {
            int gr = mbase + mf * 16 + rs * 8;
            if (gr >= cnt) continue;
            int   tok = g_tok[e * MAX_T + gr];
            float wgt = g_w[e * MAX_T + gr];
            float* orow = out + (size_t)tok * D_MODEL;
#pragma unroll
            for (int nf = 0; nf < 4; nf++) {
                int n = n0 + wn * 32 + nf * 8 + cb;
                atomicAdd(&orow[n],     wgt * (d[mf][nf][rs * 2 + 0] + bde[n]));
                atomicAdd(&orow[n + 1], wgt * (d[mf][nf][rs * 2 + 1] + bde[n + 1]));
            }
        }
    }
}

// ---------------- launch ----------------
extern "C" void kernel_launch(void* const* d_in, const int* in_sizes, int n_in,
                              void* d_out, int out_size) {
    const float* x  = (const float*)d_in[0];
    const float* Wr = (const float*)d_in[1];
    const float* br = (const float*)d_in[2];
    const float* Wg = (const float*)d_in[3];
    const float* bg = (const float*)d_in[4];
    const float* Wu = (const float*)d_in[5];
    const float* bu = (const float*)d_in[6];
    const float* Wd = (const float*)d_in[7];
    const float* bd = (const float*)d_in[8];
    float* out = (float*)d_out;

    int T = in_sizes[0] / D_MODEL;   // 2048

    const int SMEM = 1024 + 2 * 32768;   // 66560
    cudaFuncSetAttribute(gemm1_tc, cudaFuncAttributeMaxDynamicSharedMemorySize, SMEM);
    cudaFuncSetAttribute(gemm2_tc, cudaFuncAttributeMaxDynamicSharedMemorySize, SMEM);

    init_kernel<<<256, 256>>>(out, out_size);
    router_kernel<<<T, 128>>>(x, Wr, br);
    offsets_kernel<<<1, 1>>>();

    dim3 g1(MAX_T / 128, D_FF / 64, NE);      // (16, 64, 8); x fastest -> B reuse in L2
    gemm1_tc<<<g1, 256, SMEM>>>(x, Wg, bg, Wu, bu);

    dim3 g2(MAX_T / 128, D_MODEL / 128, NE);  // (16, 8, 8)
    gemm2_tc<<<g2, 256, SMEM>>>(Wd, bd, out);
}

// round 7
// speedup vs baseline: 3.2286x; 1.1293x over previous
#include <cuda_runtime.h>
#include <math.h>

#define D_MODEL 1024
#define D_FF    4096
#define NE      8
#define MAX_T   2048
#define BK      32

// ---------------- scratch (static __device__, no allocations) ----------------
__device__ int   g_counts[NE];
__device__ int   g_offsets[NE];
__device__ int   g_tok[NE * MAX_T];
__device__ float g_w[NE * MAX_T];
__device__ float g_H[(size_t)(2 * MAX_T) * D_FF];   // 64 MB compact hidden acts

// ---------------- helpers ----------------
__device__ __forceinline__ unsigned smem_u32(const void* p) {
    unsigned a;
    asm("{ .reg .u64 t; cvta.to.shared.u64 t, %1; cvt.u32.u64 %0, t; }" : "=r"(a) : "l"(p));
    return a;
}
__device__ __forceinline__ void sts_tf32x4(unsigned addr, float4 v) {
    asm volatile("{ .reg .b32 a,b,c,d;\n\t"
                 "cvt.rna.tf32.f32 a, %1; cvt.rna.tf32.f32 b, %2;\n\t"
                 "cvt.rna.tf32.f32 c, %3; cvt.rna.tf32.f32 d, %4;\n\t"
                 "st.shared.v4.b32 [%0], {a,b,c,d}; }"
                 :: "r"(addr), "f"(v.x), "f"(v.y), "f"(v.z), "f"(v.w) : "memory");
}
__device__ __forceinline__ void ldm_x4(unsigned& r0, unsigned& r1, unsigned& r2, unsigned& r3,
                                       unsigned addr) {
    asm volatile("ldmatrix.sync.aligned.m8n8.x4.shared.b16 {%0,%1,%2,%3}, [%4];"
                 : "=r"(r0), "=r"(r1), "=r"(r2), "=r"(r3) : "r"(addr));
}
__device__ __forceinline__ void mma_frag(float* d, const unsigned* a, const unsigned* b) {
    asm volatile("mma.sync.aligned.m16n8k8.row.col.f32.tf32.tf32.f32 "
                 "{%0,%1,%2,%3}, {%4,%5,%6,%7}, {%8,%9}, {%0,%1,%2,%3};"
                 : "+f"(d[0]), "+f"(d[1]), "+f"(d[2]), "+f"(d[3])
                 : "r"(a[0]), "r"(a[1]), "r"(a[2]), "r"(a[3]), "r"(b[0]), "r"(b[1]));
}
#define SWZ(o) ((o) ^ (((o) >> 3) & 0x70))
#define STAGE_BYTES 49152u   // A 16KB + B 32KB

// ---------------- init: zero counts + output ----------------
__global__ void init_kernel(float* __restrict__ out, int n_out) {
    int i = blockIdx.x * blockDim.x + threadIdx.x;
    if (i < NE) g_counts[i] = 0;
    int stride = gridDim.x * blockDim.x;
    for (int j = i; j < n_out; j += stride) out[j] = 0.0f;
}

// ---------------- router (validated) ----------------
__global__ void router_kernel(const float* __restrict__ x,
                              const float* __restrict__ Wr,
                              const float* __restrict__ br) {
    const int t = blockIdx.x;
    const int tid = threadIdx.x;  // 128 threads
    float acc[NE];
#pragma unroll
    for (int e = 0; e < NE; e++) acc[e] = 0.0f;
    const float* xr = x + (size_t)t * D_MODEL;
    for (int d = tid; d < D_MODEL; d += 128) {
        float xv = xr[d];
        const float4* w4 = reinterpret_cast<const float4*>(Wr + (size_t)d * NE);
        float4 a = w4[0], b = w4[1];
        acc[0] += xv * a.x; acc[1] += xv * a.y;
        acc[2] += xv * a.z; acc[3] += xv * a.w;
        acc[4] += xv * b.x; acc[5] += xv * b.y;
        acc[6] += xv * b.z; acc[7] += xv * b.w;
    }
    __shared__ float red[128][NE];
#pragma unroll
    for (int e = 0; e < NE; e++) red[tid][e] = acc[e];
    __syncthreads();
    for (int s = 64; s > 0; s >>= 1) {
        if (tid < s) {
#pragma unroll
            for (int e = 0; e < NE; e++) red[tid][e] += red[tid + s][e];
        }
        __syncthreads();
    }
    if (tid == 0) {
        float l[NE];
#pragma unroll
        for (int e = 0; e < NE; e++) l[e] = red[0][e] + br[e];
        int i0 = 0;
#pragma unroll
        for (int e = 1; e < NE; e++) if (l[e] > l[i0]) i0 = e;
        int i1 = (i0 == 0) ? 1 : 0;
#pragma unroll
        for (int e = 0; e < NE; e++) if (e != i0 && l[e] > l[i1]) i1 = e;
        float m  = fmaxf(l[i0], l[i1]);
        float e0 = expf(l[i0] - m), e1 = expf(l[i1] - m);
        float inv = 1.0f / (e0 + e1);
        int p0 = atomicAdd(&g_counts[i0], 1);
        g_tok[i0 * MAX_T + p0] = t;  g_w[i0 * MAX_T + p0] = e0 * inv;
        int p1 = atomicAdd(&g_counts[i1], 1);
        g_tok[i1 * MAX_T + p1] = t;  g_w[i1 * MAX_T + p1] = e1 * inv;
    }
}

__global__ void offsets_kernel() {
    int off = 0;
#pragma unroll
    for (int e = 0; e < NE; e++) { g_offsets[e] = off; off += g_counts[e]; }
}

// =====================================================================
// GEMM1: CTA = 128 tokens x 128 f (gate AND up fused; B tile 256 rows:
// rows [0,128) = gate f, [128,256) = up f). K=1024, BK=32.
// 8 warps (2m x 4n), warp tile 64m x 64n (32 gate f + 32 up f, matching).
// Single __syncthreads per stage.
// =====================================================================
__global__ __launch_bounds__(256, 1) void gemm1_tc(
    const float* __restrict__ x,
    const float* __restrict__ Wg, const float* __restrict__ bg,
    const float* __restrict__ Wu, const float* __restrict__ bu) {
    const int e   = blockIdx.z;
    const int cnt = g_counts[e];
    const int m0  = blockIdx.x * 128;
    if (m0 >= cnt) return;
    const int f0  = blockIdx.y * 128;

    extern __shared__ char dsm[];
    const unsigned sbase = (smem_u32(dsm) + 1023u) & ~1023u;

    const int tid = threadIdx.x, wid = tid >> 5, lane = tid & 31;
    const int wm = wid & 1, wn = wid >> 1;

    // A gather
    const int ar = tid >> 1, ah = tid & 1;
    const float* ap = nullptr;
    if (m0 + ar < cnt) ap = x + (size_t)g_tok[e * MAX_T + m0 + ar] * D_MODEL + ah * 16;
    const float* wgp = Wg + (size_t)e * D_MODEL * D_FF + f0;
    const float* wup = Wu + (size_t)e * D_MODEL * D_FF + f0;
    const int kr = wid * 4;

    // ldmatrix lane constants
    const unsigned xmask = (unsigned)((lane & 7) << 4);
    const int mrow = ((lane >> 3) & 1) * 8 + (lane & 7);
    const unsigned akh = (unsigned)((lane >> 4) * 16);
    const int nrow = ((lane >> 4) * 8) + (lane & 7);
    const unsigned bkh = (unsigned)(((lane >> 3) & 1) * 16);

    float d[4][8][4];
#pragma unroll
    for (int i = 0; i < 4; i++)
#pragma unroll
        for (int j = 0; j < 8; j++)
#pragma unroll
            for (int q = 0; q < 4; q++) d[i][j][q] = 0.f;

    float4 pa[4];
    float  pb[8][4];   // j<4: gate rows lane+32j ; j>=4: up rows lane+32(j-4)

    auto ldg = [&](int k0) {
#pragma unroll
        for (int q = 0; q < 4; q++) {
            pa[q] = make_float4(0.f, 0.f, 0.f, 0.f);
            if (ap) pa[q] = *reinterpret_cast<const float4*>(ap + k0 + q * 4);
        }
#pragma unroll
        for (int i = 0; i < 4; i++) {
            size_t ro = (size_t)(k0 + kr + i) * D_FF;
#pragma unroll
            for (int j = 0; j < 4; j++) {
                pb[j][i]     = wgp[ro + lane + 32 * j];
                pb[j + 4][i] = wup[ro + lane + 32 * j];
            }
        }
    };
    auto sts = [&](int buf) {
        unsigned Ab = sbase + (unsigned)buf * STAGE_BYTES;
        unsigned Bb = Ab + 16384u;
#pragma unroll
        for (int q = 0; q < 4; q++)
            sts_tf32x4(Ab + SWZ((unsigned)(ar * 128 + ah * 64 + q * 16)), pa[q]);
#pragma unroll
        for (int j = 0; j < 8; j++) {
            int row = (j < 4) ? (lane + 32 * j) : (128 + lane + 32 * (j - 4));
            sts_tf32x4(Bb + SWZ((unsigned)(row * 128 + wid * 16)),
                       make_float4(pb[j][0], pb[j][1], pb[j][2], pb[j][3]));
        }
    };
    auto comp = [&](int buf) {
        unsigned Ab = sbase + (unsigned)buf * STAGE_BYTES;
        unsigned Bb = Ab + 16384u;
#pragma unroll
        for (int ks = 0; ks < 4; ks++) {
            unsigned a[4][4];
#pragma unroll
            for (int mf = 0; mf < 4; mf++)
                ldm_x4(a[mf][0], a[mf][1], a[mf][2], a[mf][3],
                       Ab + (unsigned)((wm * 64 + mf * 16 + mrow) * 128) +
                       ((akh + ks * 32) ^ xmask));
            unsigned b[8][2];
#pragma unroll
            for (int g = 0; g < 2; g++)
#pragma unroll
                for (int nf2 = 0; nf2 < 2; nf2++) {
                    int bi = g * 4 + nf2 * 2;
                    ldm_x4(b[bi][0], b[bi][1], b[bi + 1][0], b[bi + 1][1],
                           Bb + (unsigned)((g * 128 + wn * 32 + nf2 * 16 + nrow) * 128) +
                           ((bkh + ks * 32) ^ xmask));
                }
#pragma unroll
            for (int mf = 0; mf < 4; mf++)
#pragma unroll
                for (int nf = 0; nf < 8; nf++)
                    mma_frag(d[mf][nf], a[mf], b[nf]);
        }
    };

    ldg(0); sts(0); __syncthreads();
    const int NST = D_MODEL / BK;   // 32
    for (int s = 0; s < NST; s++) {
        if (s + 1 < NST) {
            ldg((s + 1) * BK);
            comp(s & 1);
            sts((s + 1) & 1);     // other buffer: freed by previous barrier
            __syncthreads();
        } else {
            comp(s & 1);
        }
    }

    // epilogue: h = silu(g+bg)*(u+bu) -> g_H  (nf<4 gate, nf>=4 up, same f)
    const int hb = g_offsets[e];
    const float* bge = bg + (size_t)e * D_FF;
    const float* bue = bu + (size_t)e * D_FF;
    const int mbase = m0 + wm * 64 + (lane >> 2);
    const int cb = (lane & 3) * 2;
#pragma unroll
    for (int mf = 0; mf < 4; mf++) {
#pragma unroll
        for (int rs = 0; rs < 2; rs++) {
            int gr = mbase + mf * 16 + rs * 8;
            if (gr >= cnt) continue;
            float* hrow = g_H + (size_t)(hb + gr) * D_FF;
#pragma unroll
            for (int nf = 0; nf < 4; nf++) {
                int f = f0 + wn * 32 + nf * 8 + cb;
                float g0 = d[mf][nf][rs * 2 + 0] + bge[f];
                float g1 = d[mf][nf][rs * 2 + 1] + bge[f + 1];
                float u0 = d[mf][nf + 4][rs * 2 + 0] + bue[f];
                float u1 = d[mf][nf + 4][rs * 2 + 1] + bue[f + 1];
                float h0 = (g0 / (1.0f + expf(-g0))) * u0;
                float h1 = (g1 / (1.0f + expf(-g1))) * u1;
                *reinterpret_cast<float2*>(hrow + f) = make_float2(h0, h1);
            }
        }
    }
}

// =====================================================================
// GEMM2: out[tok] += w * (H @ Wd + bd). CTA 128 x 256, K=4096, BK=32.
// 8 warps (2m x 4n), warp 64x64 (rows wn*32..+31 and 128+wn*32..+31).
// =====================================================================
__global__ __launch_bounds__(256, 1) void gemm2_tc(
    const float* __restrict__ Wd, const float* __restrict__ bd,
    float* __restrict__ out) {
    const int e   = blockIdx.z;
    const int cnt = g_counts[e];
    const int m0  = blockIdx.x * 128;
    if (m0 >= cnt) return;
    const int n0  = blockIdx.y * 256;

    extern __shared__ char dsm[];
    const unsigned sbase = (smem_u32(dsm) + 1023u) & ~1023u;

    const int tid = threadIdx.x, wid = tid >> 5, lane = tid & 31;
    const int wm = wid & 1, wn = wid >> 1;

    const int hb = g_offsets[e];
    const int ar = tid >> 1, ah = tid & 1;
    const float* ap = nullptr;
    if (m0 + ar < cnt) ap = g_H + (size_t)(hb + m0 + ar) * D_FF + ah * 16;
    const float* wdp = Wd + (size_t)e * D_FF * D_MODEL + n0;
    const int kr = wid * 4;

    const unsigned xmask = (unsigned)((lane & 7) << 4);
    const int mrow = ((lane >> 3) & 1) * 8 + (lane & 7);
    const unsigned akh = (unsigned)((lane >> 4) * 16);
    const int nrow = ((lane >> 4) * 8) + (lane & 7);
    const unsigned bkh = (unsigned)(((lane >> 3) & 1) * 16);

    float d[4][8][4];
#pragma unroll
    for (int i = 0; i < 4; i++)
#pragma unroll
        for (int j = 0; j < 8; j++)
#pragma unroll
            for (int q = 0; q < 4; q++) d[i][j][q] = 0.f;

    float4 pa[4];
    float  pb[8][4];

    auto ldg = [&](int k0) {
#pragma unroll
        for (int q = 0; q < 4; q++) {
            pa[q] = make_float4(0.f, 0.f, 0.f, 0.f);
            if (ap) pa[q] = *reinterpret_cast<const float4*>(ap + k0 + q * 4);
        }
#pragma unroll
        for (int i = 0; i < 4; i++) {
            size_t ro = (size_t)(k0 + kr + i) * D_MODEL;
#pragma unroll
            for (int j = 0; j < 8; j++)
                pb[j][i] = wdp[ro + lane + 32 * j];
        }
    };
    auto sts = [&](int buf) {
        unsigned Ab = sbase + (unsigned)buf * STAGE_BYTES;
        unsigned Bb = Ab + 16384u;
#pragma unroll
        for (int q = 0; q < 4; q++)
            sts_tf32x4(Ab + SWZ((unsigned)(ar * 128 + ah * 64 + q * 16)), pa[q]);
#pragma unroll
        for (int j = 0; j < 8; j++)
            sts_tf32x4(Bb + SWZ((unsigned)((lane + 32 * j) * 128 + wid * 16)),
                       make_float4(pb[j][0], pb[j][1], pb[j][2], pb[j][3]));
    };
    auto comp = [&](int buf) {
        unsigned Ab = sbase + (unsigned)buf * STAGE_BYTES;
        unsigned Bb = Ab + 16384u;
#pragma unroll
        for (int ks = 0; ks < 4; ks++) {
            unsigned a[4][4];
#pragma unroll
            for (int mf = 0; mf < 4; mf++)
                ldm_x4(a[mf][0], a[mf][1], a[mf][2], a[mf][3],
                       Ab + (unsigned)((wm * 64 + mf * 16 + mrow) * 128) +
                       ((akh + ks * 32) ^ xmask));
            unsigned b[8][2];
#pragma unroll
            for (int g = 0; g < 2; g++)
#pragma unroll
                for (int nf2 = 0; nf2 < 2; nf2++) {
                    int bi = g * 4 + nf2 * 2;
                    ldm_x4(b[bi][0], b[bi][1], b[bi + 1][0], b[bi + 1][1],
                           Bb + (unsigned)((g * 128 + wn * 32 + nf2 * 16 + nrow) * 128) +
                           ((bkh + ks * 32) ^ xmask));
                }
#pragma unroll
            for (int mf = 0; mf < 4; mf++)
#pragma unroll
                for (int nf = 0; nf < 8; nf++)
                    mma_frag(d[mf][nf], a[mf], b[nf]);
        }
    };

    ldg(0); sts(0); __syncthreads();
    const int NST = D_FF / BK;   // 128
    for (int s = 0; s < NST; s++) {
        if (s + 1 < NST) {
            ldg((s + 1) * BK);
            comp(s & 1);
            sts((s + 1) & 1);
            __syncthreads();
        } else {
            comp(s & 1);
        }
    }

    // epilogue: out[tok, n] += w * (acc + bd); nf<4 -> n block wn*32, nf>=4 -> +128
    const float* bde = bd + (size_t)e * D_MODEL;
    const int mbase = m0 + wm * 64 + (lane >> 2);
    const int cb = (lane & 3) * 2;
#pragma unroll
    for (int mf = 0; mf < 4; mf++) {
#pragma unroll
        for (int rs = 0; rs < 2; rs++) {
            int gr = mbase + mf * 16 + rs * 8;
            if (gr >= cnt) continue;
            int   tok = g_tok[e * MAX_T + gr];
            float wgt = g_w[e * MAX_T + gr];
            float* orow = out + (size_t)tok * D_MODEL;
#pragma unroll
            for (int nf = 0; nf < 8; nf++) {
                int n = n0 + ((nf < 4) ? (wn * 32 + nf * 8) : (128 + wn * 32 + (nf - 4) * 8)) + cb;
                atomicAdd(&orow[n],     wgt * (d[mf][nf][rs * 2 + 0] + bde[n]));
                atomicAdd(&orow[n + 1], wgt * (d[mf][nf][rs * 2 + 1] + bde[n + 1]));
            }
        }
    }
}

// ---------------- launch ----------------
extern "C" void kernel_launch(void* const* d_in, const int* in_sizes, int n_in,
                              void* d_out, int out_size) {
    const float* x  = (const float*)d_in[0];
    const float* Wr = (const float*)d_in[1];
    const float* br = (const float*)d_in[2];
    const float* Wg = (const float*)d_in[3];
    const float* bg = (const float*)d_in[4];
    const float* Wu = (const float*)d_in[5];
    const float* bu = (const float*)d_in[6];
    const float* Wd = (const float*)d_in[7];
    const float* bd = (const float*)d_in[8];
    float* out = (float*)d_out;

    int T = in_sizes[0] / D_MODEL;   // 2048

    const int SMEM = 1024 + 2 * 49152;   // 99328
    cudaFuncSetAttribute(gemm1_tc, cudaFuncAttributeMaxDynamicSharedMemorySize, SMEM);
    cudaFuncSetAttribute(gemm2_tc, cudaFuncAttributeMaxDynamicSharedMemorySize, SMEM);

    init_kernel<<<256, 256>>>(out, out_size);
    router_kernel<<<T, 128>>>(x, Wr, br);
    offsets_kernel<<<1, 1>>>();

    dim3 g1(MAX_T / 128, D_FF / 128, NE);     // (16, 32, 8); x fastest -> B reuse in L2
    gemm1_tc<<<g1, 256, SMEM>>>(x, Wg, bg, Wu, bu);

    dim3 g2(MAX_T / 128, D_MODEL / 256, NE);  // (16, 4, 8)
    gemm2_tc<<<g2, 256, SMEM>>>(Wd, bd, out);
}

// round 10
// speedup vs baseline: 4.4220x; 1.3696x over previous
#include <cuda_runtime.h>
#include <cuda_fp16.h>
#include <math.h>

#define D_MODEL 1024
#define D_FF    4096
#define NE      8
#define MAX_T   2048
#define BK      32
#define ROWB    80u       // padded smem row stride (bytes): conflict-free ldmatrix
#define A_BYTES (128u * ROWB)
#define STAGE_BYTES (2u * 128u * ROWB)   // A tile + B tile

// ---------------- scratch (static __device__, no allocations) ----------------
__device__ int    g_counts[NE];
__device__ int    g_offsets[NE];
__device__ int    g_tok[NE * MAX_T];
__device__ float  g_w[NE * MAX_T];
__device__ __half g_H[(size_t)(2 * MAX_T) * D_FF];   // 32 MB compact hidden acts (fp16)

// ---------------- helpers ----------------
__device__ __forceinline__ unsigned smem_u32(const void* p) {
    unsigned a;
    asm("{ .reg .u64 t; cvta.to.shared.u64 t, %1; cvt.u32.u64 %0, t; }" : "=r"(a) : "l"(p));
    return a;
}
// pack two fp32 -> f16x2 (round-to-nearest-even), lo = first arg
__device__ __forceinline__ unsigned pk(float lo, float hi) {
    unsigned r;
    asm("cvt.rn.f16x2.f32 %0, %1, %2;" : "=r"(r) : "f"(hi), "f"(lo));
    return r;
}
__device__ __forceinline__ void sts64(unsigned a, unsigned x, unsigned y) {
    asm volatile("st.shared.v2.b32 [%0], {%1,%2};" :: "r"(a), "r"(x), "r"(y) : "memory");
}
__device__ __forceinline__ void sts128r(unsigned a, unsigned x, unsigned y, unsigned z, unsigned w) {
    asm volatile("st.shared.v4.b32 [%0], {%1,%2,%3,%4};" :: "r"(a), "r"(x), "r"(y), "r"(z), "r"(w) : "memory");
}
__device__ __forceinline__ void ldm_x4(unsigned& r0, unsigned& r1, unsigned& r2, unsigned& r3,
                                       unsigned addr) {
    asm volatile("ldmatrix.sync.aligned.m8n8.x4.shared.b16 {%0,%1,%2,%3}, [%4];"
                 : "=r"(r0), "=r"(r1), "=r"(r2), "=r"(r3) : "r"(addr));
}
__device__ __forceinline__ void mma16816(float* d, const unsigned* a, const unsigned* b) {
    asm volatile("mma.sync.aligned.m16n8k16.row.col.f32.f16.f16.f32 "
                 "{%0,%1,%2,%3}, {%4,%5,%6,%7}, {%8,%9}, {%0,%1,%2,%3};"
                 : "+f"(d[0]), "+f"(d[1]), "+f"(d[2]), "+f"(d[3])
                 : "r"(a[0]), "r"(a[1]), "r"(a[2]), "r"(a[3]), "r"(b[0]), "r"(b[1]));
}
__device__ __forceinline__ void cpa16(unsigned dst, const void* src, int sz) {
    asm volatile("cp.async.cg.shared.global [%0], [%1], 16, %2;"
                 :: "r"(dst), "l"(src), "r"(sz) : "memory");
}
__device__ __forceinline__ void cpa_commit() { asm volatile("cp.async.commit_group;" ::: "memory"); }
__device__ __forceinline__ void cpa_wait0()  { asm volatile("cp.async.wait_group 0;"  ::: "memory"); }

// ---------------- init: zero counts + output ----------------
__global__ void init_kernel(float* __restrict__ out, int n_out) {
    int i = blockIdx.x * blockDim.x + threadIdx.x;
    if (i < NE) g_counts[i] = 0;
    int stride = gridDim.x * blockDim.x;
    for (int j = i; j < n_out; j += stride) out[j] = 0.0f;
}

// ---------------- router (validated) ----------------
__global__ void router_kernel(const float* __restrict__ x,
                              const float* __restrict__ Wr,
                              const float* __restrict__ br) {
    const int t = blockIdx.x;
    const int tid = threadIdx.x;  // 128 threads
    float acc[NE];
#pragma unroll
    for (int e = 0; e < NE; e++) acc[e] = 0.0f;
    const float* xr = x + (size_t)t * D_MODEL;
    for (int d = tid; d < D_MODEL; d += 128) {
        float xv = xr[d];
        const float4* w4 = reinterpret_cast<const float4*>(Wr + (size_t)d * NE);
        float4 a = w4[0], b = w4[1];
        acc[0] += xv * a.x; acc[1] += xv * a.y;
        acc[2] += xv * a.z; acc[3] += xv * a.w;
        acc[4] += xv * b.x; acc[5] += xv * b.y;
        acc[6] += xv * b.z; acc[7] += xv * b.w;
    }
    __shared__ float red[128][NE];
#pragma unroll
    for (int e = 0; e < NE; e++) red[tid][e] = acc[e];
    __syncthreads();
    for (int s = 64; s > 0; s >>= 1) {
        if (tid < s) {
#pragma unroll
            for (int e = 0; e < NE; e++) red[tid][e] += red[tid + s][e];
        }
        __syncthreads();
    }
    if (tid == 0) {
        float l[NE];
#pragma unroll
        for (int e = 0; e < NE; e++) l[e] = red[0][e] + br[e];
        int i0 = 0;
#pragma unroll
        for (int e = 1; e < NE; e++) if (l[e] > l[i0]) i0 = e;
        int i1 = (i0 == 0) ? 1 : 0;
#pragma unroll
        for (int e = 0; e < NE; e++) if (e != i0 && l[e] > l[i1]) i1 = e;
        float m  = fmaxf(l[i0], l[i1]);
        float e0 = expf(l[i0] - m), e1 = expf(l[i1] - m);
        float inv = 1.0f / (e0 + e1);
        int p0 = atomicAdd(&g_counts[i0], 1);
        g_tok[i0 * MAX_T + p0] = t;  g_w[i0 * MAX_T + p0] = e0 * inv;
        int p1 = atomicAdd(&g_counts[i1], 1);
        g_tok[i1 * MAX_T + p1] = t;  g_w[i1 * MAX_T + p1] = e1 * inv;
    }
}

__global__ void offsets_kernel() {
    int off = 0;
#pragma unroll
    for (int e = 0; e < NE; e++) { g_offsets[e] = off; off += g_counts[e]; }
}

// =====================================================================
// GEMM1 (fp16 mma m16n8k16): CTA = 128 tokens x 64 f (gate+up fused; B tile
// 128 rows: [0,64)=gate f, [64,128)=up f). K=1024, BK=32, 8 warps (2m x 4n),
// warp tile 64m x 32n (16 gate + 16 up). 2 CTAs/SM. Single sync per stage.
// =====================================================================
__global__ __launch_bounds__(256, 2) void gemm1_tc(
    const float* __restrict__ x,
    const float* __restrict__ Wg, const float* __restrict__ bg,
    const float* __restrict__ Wu, const float* __restrict__ bu) {
    const int e   = blockIdx.z;
    const int cnt = g_counts[e];
    const int m0  = blockIdx.x * 128;
    if (m0 >= cnt) return;
    const int f0  = blockIdx.y * 64;

    extern __shared__ char dsm[];
    const unsigned sbase = (smem_u32(dsm) + 1023u) & ~1023u;

    const int tid = threadIdx.x, wid = tid >> 5, lane = tid & 31;
    const int wm = wid & 1, wn = wid >> 1;

    // A gather
    const int ar = tid >> 1, ah = tid & 1;
    const float* ap = nullptr;
    if (m0 + ar < cnt) ap = x + (size_t)g_tok[e * MAX_T + m0 + ar] * D_MODEL + ah * 16;
    const float* wgp = Wg + (size_t)e * D_MODEL * D_FF + f0;
    const float* wup = Wu + (size_t)e * D_MODEL * D_FF + f0;
    const int kr = wid * 4;

    float d[4][4][4];
#pragma unroll
    for (int i = 0; i < 4; i++)
#pragma unroll
        for (int j = 0; j < 4; j++)
#pragma unroll
            for (int q = 0; q < 4; q++) d[i][j][q] = 0.f;

    unsigned pa[8], pb[8];

    auto ldg = [&](int k0) {
#pragma unroll
        for (int q = 0; q < 4; q++) {
            float4 v = make_float4(0.f, 0.f, 0.f, 0.f);
            if (ap) v = *reinterpret_cast<const float4*>(ap + k0 + q * 4);
            pa[q * 2] = pk(v.x, v.y); pa[q * 2 + 1] = pk(v.z, v.w);
        }
#pragma unroll
        for (int j = 0; j < 4; j++) {
            const float* wp = (j < 2) ? wgp : wup;
            const float* p = wp + (size_t)(k0 + kr) * D_FF + lane + 32 * (j & 1);
            float w0 = p[0], w1 = p[D_FF], w2 = p[2 * D_FF], w3 = p[3 * D_FF];
            pb[j * 2] = pk(w0, w1); pb[j * 2 + 1] = pk(w2, w3);
        }
    };
    auto sts = [&](int buf) {
        unsigned Ab = sbase + (unsigned)buf * STAGE_BYTES;
        unsigned Bb = Ab + A_BYTES;
        unsigned aa = Ab + (unsigned)(ar * ROWB + ah * 32);
        sts128r(aa,      pa[0], pa[1], pa[2], pa[3]);
        sts128r(aa + 16, pa[4], pa[5], pa[6], pa[7]);
#pragma unroll
        for (int j = 0; j < 4; j++) {
            int row = (j >> 1) * 64 + lane + 32 * (j & 1);
            sts64(Bb + (unsigned)(row * ROWB + kr * 2), pb[j * 2], pb[j * 2 + 1]);
        }
    };
    auto comp = [&](int buf) {
        unsigned Ab = sbase + (unsigned)buf * STAGE_BYTES;
        unsigned Bb = Ab + A_BYTES;
        const int arow = wm * 64 + ((lane >> 3) & 1) * 8 + (lane & 7);
        const int brow = wn * 16 + (lane >> 4) * 8 + (lane & 7);
#pragma unroll
        for (int ks = 0; ks < 2; ks++) {
            unsigned a[4][4];
#pragma unroll
            for (int mf = 0; mf < 4; mf++)
                ldm_x4(a[mf][0], a[mf][1], a[mf][2], a[mf][3],
                       Ab + (unsigned)((arow + mf * 16) * ROWB) +
                       (unsigned)((ks * 2 + (lane >> 4)) * 16));
            unsigned b[4][2];
#pragma unroll
            for (int g = 0; g < 2; g++)
                ldm_x4(b[2 * g][0], b[2 * g][1], b[2 * g + 1][0], b[2 * g + 1][1],
                       Bb + (unsigned)((g * 64 + brow) * ROWB) +
                       (unsigned)((ks * 2 + ((lane >> 3) & 1)) * 16));
#pragma unroll
            for (int mf = 0; mf < 4; mf++)
#pragma unroll
                for (int nf = 0; nf < 4; nf++)
                    mma16816(d[mf][nf], a[mf], b[nf]);
        }
    };

    ldg(0); sts(0); __syncthreads();
    const int NST = D_MODEL / BK;   // 32
    for (int s = 0; s < NST; s++) {
        if (s + 1 < NST) {
            ldg((s + 1) * BK);
            comp(s & 1);
            sts((s + 1) & 1);     // other buffer: freed by previous barrier
            __syncthreads();
        } else {
            comp(s & 1);
        }
    }

    // epilogue: h = silu(g+bg)*(u+bu) -> g_H fp16 (nf<2 gate, nf>=2 up, same f)
    const int hb = g_offsets[e];
    const float* bge = bg + (size_t)e * D_FF;
    const float* bue = bu + (size_t)e * D_FF;
    const int mbase = m0 + wm * 64 + (lane >> 2);
    const int cb = (lane & 3) * 2;
#pragma unroll
    for (int mf = 0; mf < 4; mf++) {
#pragma unroll
        for (int rs = 0; rs < 2; rs++) {
            int gr = mbase + mf * 16 + rs * 8;
            if (gr >= cnt) continue;
            __half* hrow = g_H + (size_t)(hb + gr) * D_FF;
#pragma unroll
            for (int nf = 0; nf < 2; nf++) {
                int f = f0 + wn * 16 + nf * 8 + cb;
                float g0 = d[mf][nf][rs * 2 + 0] + bge[f];
                float g1 = d[mf][nf][rs * 2 + 1] + bge[f + 1];
                float u0 = d[mf][nf + 2][rs * 2 + 0] + bue[f];
                float u1 = d[mf][nf + 2][rs * 2 + 1] + bue[f + 1];
                float h0 = (g0 / (1.0f + expf(-g0))) * u0;
                float h1 = (g1 / (1.0f + expf(-g1))) * u1;
                *reinterpret_cast<__half2*>(hrow + f) = __floats2half2_rn(h0, h1);
            }
        }
    }
}

// =====================================================================
// GEMM2 (fp16): out[tok] += w * (H @ Wd + bd). CTA 128 x 128, K=4096, BK=32.
// A (g_H, already fp16) via cp.async; B (Wd fp32) via ldg+cvt. Warp 64x32.
// =====================================================================
__global__ __launch_bounds__(256, 2) void gemm2_tc(
    const float* __restrict__ Wd, const float* __restrict__ bd,
    float* __restrict__ out) {
    const int e   = blockIdx.z;
    const int cnt = g_counts[e];
    const int m0  = blockIdx.x * 128;
    if (m0 >= cnt) return;
    const int n0  = blockIdx.y * 128;

    extern __shared__ char dsm[];
    const unsigned sbase = (smem_u32(dsm) + 1023u) & ~1023u;

    const int tid = threadIdx.x, wid = tid >> 5, lane = tid & 31;
    const int wm = wid & 1, wn = wid >> 1;

    const int hb = g_offsets[e];
    const int ar = tid >> 1, ah = tid & 1;
    const int arow_ok = (m0 + ar < cnt);
    int hrowi = hb + m0 + ar; if (hrowi > 2 * MAX_T - 1) hrowi = 2 * MAX_T - 1;
    const __half* ap = g_H + (size_t)hrowi * D_FF + ah * 16;
    const int asz = arow_ok ? 16 : 0;
    const float* wdp = Wd + (size_t)e * D_FF * D_MODEL + n0;
    const int kr = wid * 4;

    float d[4][4][4];
#pragma unroll
    for (int i = 0; i < 4; i++)
#pragma unroll
        for (int j = 0; j < 4; j++)
#pragma unroll
            for (int q = 0; q < 4; q++) d[i][j][q] = 0.f;

    unsigned pb[8];

    auto ldg = [&](int k0, int buf) {
        // A: cp.async straight from fp16 g_H (2 x 16B per thread)
        unsigned Ab = sbase + (unsigned)buf * STAGE_BYTES;
        unsigned aa = Ab + (unsigned)(ar * ROWB + ah * 32);
        cpa16(aa,      ap + k0,     asz);
        cpa16(aa + 16, ap + k0 + 8, asz);
        cpa_commit();
        // B: ldg + pack
#pragma unroll
        for (int j = 0; j < 4; j++) {
            const float* p = wdp + (size_t)(k0 + kr) * D_MODEL + lane + 32 * j;
            float w0 = p[0], w1 = p[D_MODEL], w2 = p[2 * D_MODEL], w3 = p[3 * D_MODEL];
            pb[j * 2] = pk(w0, w1); pb[j * 2 + 1] = pk(w2, w3);
        }
    };
    auto sts = [&](int buf) {
        unsigned Bb = sbase + (unsigned)buf * STAGE_BYTES + A_BYTES;
#pragma unroll
        for (int j = 0; j < 4; j++)
            sts64(Bb + (unsigned)((lane + 32 * j) * ROWB + kr * 2), pb[j * 2], pb[j * 2 + 1]);
    };
    auto comp = [&](int buf) {
        unsigned Ab = sbase + (unsigned)buf * STAGE_BYTES;
        unsigned Bb = Ab + A_BYTES;
        const int arow = wm * 64 + ((lane >> 3) & 1) * 8 + (lane & 7);
        const int brow = wn * 32 + (lane >> 4) * 8 + (lane & 7);
#pragma unroll
        for (int ks = 0; ks < 2; ks++) {
            unsigned a[4][4];
#pragma unroll
            for (int mf = 0; mf < 4; mf++)
                ldm_x4(a[mf][0], a[mf][1], a[mf][2], a[mf][3],
                       Ab + (unsigned)((arow + mf * 16) * ROWB) +
                       (unsigned)((ks * 2 + (lane >> 4)) * 16));
            unsigned b[4][2];
#pragma unroll
            for (int g = 0; g < 2; g++)
                ldm_x4(b[2 * g][0], b[2 * g][1], b[2 * g + 1][0], b[2 * g + 1][1],
                       Bb + (unsigned)((brow + g * 16) * ROWB) +
                       (unsigned)((ks * 2 + ((lane >> 3) & 1)) * 16));
#pragma unroll
            for (int mf = 0; mf < 4; mf++)
#pragma unroll
                for (int nf = 0; nf < 4; nf++)
                    mma16816(d[mf][nf], a[mf], b[nf]);
        }
    };

    ldg(0, 0); sts(0); cpa_wait0(); __syncthreads();
    const int NST = D_FF / BK;   // 128
    for (int s = 0; s < NST; s++) {
        if (s + 1 < NST) {
            ldg((s + 1) * BK, (s + 1) & 1);
            comp(s & 1);
            sts((s + 1) & 1);
            cpa_wait0();
            __syncthreads();
        } else {
            comp(s & 1);
        }
    }

    // epilogue: out[tok, n] += w * (acc + bd)
    const float* bde = bd + (size_t)e * D_MODEL;
    const int mbase = m0 + wm * 64 + (lane >> 2);
    const int cb = (lane & 3) * 2;
#pragma unroll
    for (int mf = 0; mf < 4; mf++) {
#pragma unroll
        for (int rs = 0; rs < 2; rs++) {
            int gr = mbase + mf * 16 + rs * 8;
            if (gr >= cnt) continue;
            int   tok = g_tok[e * MAX_T + gr];
            float wgt = g_w[e * MAX_T + gr];
            float* orow = out + (size_t)tok * D_MODEL;
#pragma unroll
            for (int nf = 0; nf < 4; nf++) {
                int n = n0 + wn * 32 + nf * 8 + cb;
                atomicAdd(&orow[n],     wgt * (d[mf][nf][rs * 2 + 0] + bde[n]));
                atomicAdd(&orow[n + 1], wgt * (d[mf][nf][rs * 2 + 1] + bde[n + 1]));
            }
        }
    }
}

// ---------------- launch ----------------
extern "C" void kernel_launch(void* const* d_in, const int* in_sizes, int n_in,
                              void* d_out, int out_size) {
    const float* x  = (const float*)d_in[0];
    const float* Wr = (const float*)d_in[1];
    const float* br = (const float*)d_in[2];
    const float* Wg = (const float*)d_in[3];
    const float* bg = (const float*)d_in[4];
    const float* Wu = (const float*)d_in[5];
    const float* bu = (const float*)d_in[6];
    const float* Wd = (const float*)d_in[7];
    const float* bd = (const float*)d_in[8];
    float* out = (float*)d_out;

    int T = in_sizes[0] / D_MODEL;   // 2048

    const int SMEM = 1024 + 2 * (int)STAGE_BYTES;   // 1024 + 40960
    cudaFuncSetAttribute(gemm1_tc, cudaFuncAttributeMaxDynamicSharedMemorySize, SMEM);
    cudaFuncSetAttribute(gemm2_tc, cudaFuncAttributeMaxDynamicSharedMemorySize, SMEM);

    init_kernel<<<256, 256>>>(out, out_size);
    router_kernel<<<T, 128>>>(x, Wr, br);
    offsets_kernel<<<1, 1>>>();

    dim3 g1(MAX_T / 128, D_FF / 64, NE);      // (16, 64, 8); x fastest -> B reuse in L2
    gemm1_tc<<<g1, 256, SMEM>>>(x, Wg, bg, Wu, bu);

    dim3 g2(MAX_T / 128, D_MODEL / 128, NE);  // (16, 8, 8)
    gemm2_tc<<<g2, 256, SMEM>>>(Wd, bd, out);
}

// round 13
// speedup vs baseline: 4.4251x; 1.0007x over previous
#include <cuda_runtime.h>
#include <cuda_fp16.h>
#include <math.h>

#define D_MODEL 1024
#define D_FF    4096
#define NE      8
#define MAX_T   2048
#define BK      32
#define ROWB    80u       // padded smem row stride (bytes): conflict-free ldmatrix
#define A_BYTES (128u * ROWB)
#define STAGE_BYTES (2u * 128u * ROWB)   // A tile + B tile

// ---------------- scratch (static __device__, no allocations) ----------------
__device__ int    g_counts[NE];
__device__ int    g_offsets[NE];
__device__ int    g_tok[NE * MAX_T];
__device__ float  g_w[NE * MAX_T];
__device__ __half g_H[(size_t)(2 * MAX_T) * D_FF];   // 32 MB compact hidden acts (fp16)

// ---------------- helpers ----------------
__device__ __forceinline__ unsigned smem_u32(const void* p) {
    unsigned a;
    asm("{ .reg .u64 t; cvta.to.shared.u64 t, %1; cvt.u32.u64 %0, t; }" : "=r"(a) : "l"(p));
    return a;
}
// pack two fp32 -> f16x2 (round-to-nearest-even), lo = first arg
__device__ __forceinline__ unsigned pk(float lo, float hi) {
    unsigned r;
    asm("cvt.rn.f16x2.f32 %0, %1, %2;" : "=r"(r) : "f"(hi), "f"(lo));
    return r;
}
__device__ __forceinline__ void sts64(unsigned a, unsigned x, unsigned y) {
    asm volatile("st.shared.v2.b32 [%0], {%1,%2};" :: "r"(a), "r"(x), "r"(y) : "memory");
}
__device__ __forceinline__ void sts128r(unsigned a, unsigned x, unsigned y, unsigned z, unsigned w) {
    asm volatile("st.shared.v4.b32 [%0], {%1,%2,%3,%4};" :: "r"(a), "r"(x), "r"(y), "r"(z), "r"(w) : "memory");
}
__device__ __forceinline__ void ldm_x4(unsigned& r0, unsigned& r1, unsigned& r2, unsigned& r3,
                                       unsigned addr) {
    asm volatile("ldmatrix.sync.aligned.m8n8.x4.shared.b16 {%0,%1,%2,%3}, [%4];"
                 : "=r"(r0), "=r"(r1), "=r"(r2), "=r"(r3) : "r"(addr));
}
__device__ __forceinline__ void mma16816(float* d, const unsigned* a, const unsigned* b) {
    asm volatile("mma.sync.aligned.m16n8k16.row.col.f32.f16.f16.f32 "
                 "{%0,%1,%2,%3}, {%4,%5,%6,%7}, {%8,%9}, {%0,%1,%2,%3};"
                 : "+f"(d[0]), "+f"(d[1]), "+f"(d[2]), "+f"(d[3])
                 : "r"(a[0]), "r"(a[1]), "r"(a[2]), "r"(a[3]), "r"(b[0]), "r"(b[1]));
}
__device__ __forceinline__ void cpa16(unsigned dst, const void* src, int sz) {
    asm volatile("cp.async.cg.shared.global [%0], [%1], 16, %2;"
                 :: "r"(dst), "l"(src), "r"(sz) : "memory");
}
__device__ __forceinline__ void cpa_commit() { asm volatile("cp.async.commit_group;" ::: "memory"); }
__device__ __forceinline__ void cpa_wait0()  { asm volatile("cp.async.wait_group 0;"  ::: "memory"); }

// ---------------- init: zero counts + output ----------------
__global__ void init_kernel(float* __restrict__ out, int n_out) {
    int i = blockIdx.x * blockDim.x + threadIdx.x;
    if (i < NE) g_counts[i] = 0;
    int stride = gridDim.x * blockDim.x;
    for (int j = i; j < n_out; j += stride) out[j] = 0.0f;
}

// ---------------- router (validated) ----------------
__global__ void router_kernel(const float* __restrict__ x,
                              const float* __restrict__ Wr,
                              const float* __restrict__ br) {
    const int t = blockIdx.x;
    const int tid = threadIdx.x;  // 128 threads
    float acc[NE];
#pragma unroll
    for (int e = 0; e < NE; e++) acc[e] = 0.0f;
    const float* xr = x + (size_t)t * D_MODEL;
    for (int d = tid; d < D_MODEL; d += 128) {
        float xv = xr[d];
        const float4* w4 = reinterpret_cast<const float4*>(Wr + (size_t)d * NE);
        float4 a = w4[0], b = w4[1];
        acc[0] += xv * a.x; acc[1] += xv * a.y;
        acc[2] += xv * a.z; acc[3] += xv * a.w;
        acc[4] += xv * b.x; acc[5] += xv * b.y;
        acc[6] += xv * b.z; acc[7] += xv * b.w;
    }
    __shared__ float red[128][NE];
#pragma unroll
    for (int e = 0; e < NE; e++) red[tid][e] = acc[e];
    __syncthreads();
    for (int s = 64; s > 0; s >>= 1) {
        if (tid < s) {
#pragma unroll
            for (int e = 0; e < NE; e++) red[tid][e] += red[tid + s][e];
        }
        __syncthreads();
    }
    if (tid == 0) {
        float l[NE];
#pragma unroll
        for (int e = 0; e < NE; e++) l[e] = red[0][e] + br[e];
        int i0 = 0;
#pragma unroll
        for (int e = 1; e < NE; e++) if (l[e] > l[i0]) i0 = e;
        int i1 = (i0 == 0) ? 1 : 0;
#pragma unroll
        for (int e = 0; e < NE; e++) if (e != i0 && l[e] > l[i1]) i1 = e;
        float m  = fmaxf(l[i0], l[i1]);
        float e0 = expf(l[i0] - m), e1 = expf(l[i1] - m);
        float inv = 1.0f / (e0 + e1);
        int p0 = atomicAdd(&g_counts[i0], 1);
        g_tok[i0 * MAX_T + p0] = t;  g_w[i0 * MAX_T + p0] = e0 * inv;
        int p1 = atomicAdd(&g_counts[i1], 1);
        g_tok[i1 * MAX_T + p1] = t;  g_w[i1 * MAX_T + p1] = e1 * inv;
    }
}

__global__ void offsets_kernel() {
    int off = 0;
#pragma unroll
    for (int e = 0; e < NE; e++) { g_offsets[e] = off; off += g_counts[e]; }
}

// =====================================================================
// GEMM1 (fp16 mma m16n8k16): CTA = 128 tokens x 64 f (gate+up fused; B tile
// 128 rows: [0,64)=gate f, [64,128)=up f). K=1024, BK=32, 8 warps (2m x 4n),
// warp tile 64m x 32n (16 gate + 16 up). 2 CTAs/SM. Single sync per stage.
// =====================================================================
__global__ __launch_bounds__(256, 2) void gemm1_tc(
    const float* __restrict__ x,
    const float* __restrict__ Wg, const float* __restrict__ bg,
    const float* __restrict__ Wu, const float* __restrict__ bu) {
    const int e   = blockIdx.z;
    const int cnt = g_counts[e];
    const int m0  = blockIdx.x * 128;
    if (m0 >= cnt) return;
    const int f0  = blockIdx.y * 64;

    extern __shared__ char dsm[];
    const unsigned sbase = (smem_u32(dsm) + 1023u) & ~1023u;

    const int tid = threadIdx.x, wid = tid >> 5, lane = tid & 31;
    const int wm = wid & 1, wn = wid >> 1;

    // A gather
    const int ar = tid >> 1, ah = tid & 1;
    const float* ap = nullptr;
    if (m0 + ar < cnt) ap = x + (size_t)g_tok[e * MAX_T + m0 + ar] * D_MODEL + ah * 16;
    const float* wgp = Wg + (size_t)e * D_MODEL * D_FF + f0;
    const float* wup = Wu + (size_t)e * D_MODEL * D_FF + f0;
    const int kr = wid * 4;

    float d[4][4][4];
#pragma unroll
    for (int i = 0; i < 4; i++)
#pragma unroll
        for (int j = 0; j < 4; j++)
#pragma unroll
            for (int q = 0; q < 4; q++) d[i][j][q] = 0.f;

    unsigned pa[8], pb[8];

    auto ldg = [&](int k0) {
#pragma unroll
        for (int q = 0; q < 4; q++) {
            float4 v = make_float4(0.f, 0.f, 0.f, 0.f);
            if (ap) v = *reinterpret_cast<const float4*>(ap + k0 + q * 4);
            pa[q * 2] = pk(v.x, v.y); pa[q * 2 + 1] = pk(v.z, v.w);
        }
#pragma unroll
        for (int j = 0; j < 4; j++) {
            const float* wp = (j < 2) ? wgp : wup;
            const float* p = wp + (size_t)(k0 + kr) * D_FF + lane + 32 * (j & 1);
            float w0 = p[0], w1 = p[D_FF], w2 = p[2 * D_FF], w3 = p[3 * D_FF];
            pb[j * 2] = pk(w0, w1); pb[j * 2 + 1] = pk(w2, w3);
        }
    };
    auto sts = [&](int buf) {
        unsigned Ab = sbase + (unsigned)buf * STAGE_BYTES;
        unsigned Bb = Ab + A_BYTES;
        unsigned aa = Ab + (unsigned)(ar * ROWB + ah * 32);
        sts128r(aa,      pa[0], pa[1], pa[2], pa[3]);
        sts128r(aa + 16, pa[4], pa[5], pa[6], pa[7]);
#pragma unroll
        for (int j = 0; j < 4; j++) {
            int row = (j >> 1) * 64 + lane + 32 * (j & 1);
            sts64(Bb + (unsigned)(row * ROWB + kr * 2), pb[j * 2], pb[j * 2 + 1]);
        }
    };
    auto comp = [&](int buf) {
        unsigned Ab = sbase + (unsigned)buf * STAGE_BYTES;
        unsigned Bb = Ab + A_BYTES;
        const int arow = wm * 64 + ((lane >> 3) & 1) * 8 + (lane & 7);
        const int brow = wn * 16 + (lane >> 4) * 8 + (lane & 7);
#pragma unroll
        for (int ks = 0; ks < 2; ks++) {
            unsigned a[4][4];
#pragma unroll
            for (int mf = 0; mf < 4; mf++)
                ldm_x4(a[mf][0], a[mf][1], a[mf][2], a[mf][3],
                       Ab + (unsigned)((arow + mf * 16) * ROWB) +
                       (unsigned)((ks * 2 + (lane >> 4)) * 16));
            unsigned b[4][2];
#pragma unroll
            for (int g = 0; g < 2; g++)
                ldm_x4(b[2 * g][0], b[2 * g][1], b[2 * g + 1][0], b[2 * g + 1][1],
                       Bb + (unsigned)((g * 64 + brow) * ROWB) +
                       (unsigned)((ks * 2 + ((lane >> 3) & 1)) * 16));
#pragma unroll
            for (int mf = 0; mf < 4; mf++)
#pragma unroll
                for (int nf = 0; nf < 4; nf++)
                    mma16816(d[mf][nf], a[mf], b[nf]);
        }
    };

    ldg(0); sts(0); __syncthreads();
    const int NST = D_MODEL / BK;   // 32
    for (int s = 0; s < NST; s++) {
        if (s + 1 < NST) {
            ldg((s + 1) * BK);
            comp(s & 1);
            sts((s + 1) & 1);     // other buffer: freed by previous barrier
            __syncthreads();
        } else {
            comp(s & 1);
        }
    }

    // epilogue: h = silu(g+bg)*(u+bu) -> g_H fp16 (nf<2 gate, nf>=2 up, same f)
    const int hb = g_offsets[e];
    const float* bge = bg + (size_t)e * D_FF;
    const float* bue = bu + (size_t)e * D_FF;
    const int mbase = m0 + wm * 64 + (lane >> 2);
    const int cb = (lane & 3) * 2;
#pragma unroll
    for (int mf = 0; mf < 4; mf++) {
#pragma unroll
        for (int rs = 0; rs < 2; rs++) {
            int gr = mbase + mf * 16 + rs * 8;
            if (gr >= cnt) continue;
            __half* hrow = g_H + (size_t)(hb + gr) * D_FF;
#pragma unroll
            for (int nf = 0; nf < 2; nf++) {
                int f = f0 + wn * 16 + nf * 8 + cb;
                float g0 = d[mf][nf][rs * 2 + 0] + bge[f];
                float g1 = d[mf][nf][rs * 2 + 1] + bge[f + 1];
                float u0 = d[mf][nf + 2][rs * 2 + 0] + bue[f];
                float u1 = d[mf][nf + 2][rs * 2 + 1] + bue[f + 1];
                float h0 = (g0 / (1.0f + expf(-g0))) * u0;
                float h1 = (g1 / (1.0f + expf(-g1))) * u1;
                *reinterpret_cast<__half2*>(hrow + f) = __floats2half2_rn(h0, h1);
            }
        }
    }
}

// =====================================================================
// GEMM2 (fp16): out[tok] += w * (H @ Wd + bd). CTA 128 x 128, K=4096, BK=32.
// A (g_H, already fp16) via cp.async; B (Wd fp32) via ldg+cvt. Warp 64x32.
// =====================================================================
__global__ __launch_bounds__(256, 2) void gemm2_tc(
    const float* __restrict__ Wd, const float* __restrict__ bd,
    float* __restrict__ out) {
    const int e   = blockIdx.z;
    const int cnt = g_counts[e];
    const int m0  = blockIdx.x * 128;
    if (m0 >= cnt) return;
    const int n0  = blockIdx.y * 128;

    extern __shared__ char dsm[];
    const unsigned sbase = (smem_u32(dsm) + 1023u) & ~1023u;

    const int tid = threadIdx.x, wid = tid >> 5, lane = tid & 31;
    const int wm = wid & 1, wn = wid >> 1;

    const int hb = g_offsets[e];
    const int ar = tid >> 1, ah = tid & 1;
    const int arow_ok = (m0 + ar < cnt);
    int hrowi = hb + m0 + ar; if (hrowi > 2 * MAX_T - 1) hrowi = 2 * MAX_T - 1;
    const __half* ap = g_H + (size_t)hrowi * D_FF + ah * 16;
    const int asz = arow_ok ? 16 : 0;
    const float* wdp = Wd + (size_t)e * D_FF * D_MODEL + n0;
    const int kr = wid * 4;

    float d[4][4][4];
#pragma unroll
    for (int i = 0; i < 4; i++)
#pragma unroll
        for (int j = 0; j < 4; j++)
#pragma unroll
            for (int q = 0; q < 4; q++) d[i][j][q] = 0.f;

    unsigned pb[8];

    auto ldg = [&](int k0, int buf) {
        // A: cp.async straight from fp16 g_H (2 x 16B per thread)
        unsigned Ab = sbase + (unsigned)buf * STAGE_BYTES;
        unsigned aa = Ab + (unsigned)(ar * ROWB + ah * 32);
        cpa16(aa,      ap + k0,     asz);
        cpa16(aa + 16, ap + k0 + 8, asz);
        cpa_commit();
        // B: ldg + pack
#pragma unroll
        for (int j = 0; j < 4; j++) {
            const float* p = wdp + (size_t)(k0 + kr) * D_MODEL + lane + 32 * j;
            float w0 = p[0], w1 = p[D_MODEL], w2 = p[2 * D_MODEL], w3 = p[3 * D_MODEL];
            pb[j * 2] = pk(w0, w1); pb[j * 2 + 1] = pk(w2, w3);
        }
    };
    auto sts = [&](int buf) {
        unsigned Bb = sbase + (unsigned)buf * STAGE_BYTES + A_BYTES;
#pragma unroll
        for (int j = 0; j < 4; j++)
            sts64(Bb + (unsigned)((lane + 32 * j) * ROWB + kr * 2), pb[j * 2], pb[j * 2 + 1]);
    };
    auto comp = [&](int buf) {
        unsigned Ab = sbase + (unsigned)buf * STAGE_BYTES;
        unsigned Bb = Ab + A_BYTES;
        const int arow = wm * 64 + ((lane >> 3) & 1) * 8 + (lane & 7);
        const int brow = wn * 32 + (lane >> 4) * 8 + (lane & 7);
#pragma unroll
        for (int ks = 0; ks < 2; ks++) {
            unsigned a[4][4];
#pragma unroll
            for (int mf = 0; mf < 4; mf++)
                ldm_x4(a[mf][0], a[mf][1], a[mf][2], a[mf][3],
                       Ab + (unsigned)((arow + mf * 16) * ROWB) +
                       (unsigned)((ks * 2 + (lane >> 4)) * 16));
            unsigned b[4][2];
#pragma unroll
            for (int g = 0; g < 2; g++)
                ldm_x4(b[2 * g][0], b[2 * g][1], b[2 * g + 1][0], b[2 * g + 1][1],
                       Bb + (unsigned)((brow + g * 16) * ROWB) +
                       (unsigned)((ks * 2 + ((lane >> 3) & 1)) * 16));
#pragma unroll
            for (int mf = 0; mf < 4; mf++)
#pragma unroll
                for (int nf = 0; nf < 4; nf++)
                    mma16816(d[mf][nf], a[mf], b[nf]);
        }
    };

    ldg(0, 0); sts(0); cpa_wait0(); __syncthreads();
    const int NST = D_FF / BK;   // 128
    for (int s = 0; s < NST; s++) {
        if (s + 1 < NST) {
            ldg((s + 1) * BK, (s + 1) & 1);
            comp(s & 1);
            sts((s + 1) & 1);
            cpa_wait0();
            __syncthreads();
        } else {
            comp(s & 1);
        }
    }

    // epilogue: out[tok, n] += w * (acc + bd)
    const float* bde = bd + (size_t)e * D_MODEL;
    const int mbase = m0 + wm * 64 + (lane >> 2);
    const int cb = (lane & 3) * 2;
#pragma unroll
    for (int mf = 0; mf < 4; mf++) {
#pragma unroll
        for (int rs = 0; rs < 2; rs++) {
            int gr = mbase + mf * 16 + rs * 8;
            if (gr >= cnt) continue;
            int   tok = g_tok[e * MAX_T + gr];
            float wgt = g_w[e * MAX_T + gr];
            float* orow = out + (size_t)tok * D_MODEL;
#pragma unroll
            for (int nf = 0; nf < 4; nf++) {
                int n = n0 + wn * 32 + nf * 8 + cb;
                atomicAdd(&orow[n],     wgt * (d[mf][nf][rs * 2 + 0] + bde[n]));
                atomicAdd(&orow[n + 1], wgt * (d[mf][nf][rs * 2 + 1] + bde[n + 1]));
            }
        }
    }
}

// ---------------- launch ----------------
extern "C" void kernel_launch(void* const* d_in, const int* in_sizes, int n_in,
                              void* d_out, int out_size) {
    const float* x  = (const float*)d_in[0];
    const float* Wr = (const float*)d_in[1];
    const float* br = (const float*)d_in[2];
    const float* Wg = (const float*)d_in[3];
    const float* bg = (const float*)d_in[4];
    const float* Wu = (const float*)d_in[5];
    const float* bu = (const float*)d_in[6];
    const float* Wd = (const float*)d_in[7];
    const float* bd = (const float*)d_in[8];
    float* out = (float*)d_out;

    int T = in_sizes[0] / D_MODEL;   // 2048

    const int SMEM = 1024 + 2 * (int)STAGE_BYTES;   // 1024 + 40960
    cudaFuncSetAttribute(gemm1_tc, cudaFuncAttributeMaxDynamicSharedMemorySize, SMEM);
    cudaFuncSetAttribute(gemm2_tc, cudaFuncAttributeMaxDynamicSharedMemorySize, SMEM);

    init_kernel<<<256, 256>>>(out, out_size);
    router_kernel<<<T, 128>>>(x, Wr, br);
    offsets_kernel<<<1, 1>>>();

    dim3 g1(MAX_T / 128, D_FF / 64, NE);      // (16, 64, 8); x fastest -> B reuse in L2
    gemm1_tc<<<g1, 256, SMEM>>>(x, Wg, bg, Wu, bu);

    dim3 g2(MAX_T / 128, D_MODEL / 128, NE);  // (16, 8, 8)
    gemm2_tc<<<g2, 256, SMEM>>>(Wd, bd, out);
}

// round 14
// speedup vs baseline: 4.4264x; 1.0003x over previous
#include <cuda_runtime.h>
#include <cuda_fp16.h>
#include <math.h>

#define D_MODEL 1024
#define D_FF    4096
#define NE      8
#define MAX_T   2048
#define BK      32
#define ROWB    80u       // padded smem row stride (bytes): conflict-free ldmatrix
#define A_BYTES (128u * ROWB)
#define STAGE_BYTES (2u * 128u * ROWB)   // A tile + B tile

// ---------------- scratch (static __device__, no allocations) ----------------
__device__ int    g_counts[NE];
__device__ int    g_offsets[NE];
__device__ int    g_tok[NE * MAX_T];
__device__ float  g_w[NE * MAX_T];
__device__ __half g_H[(size_t)(2 * MAX_T) * D_FF];   // 32 MB compact hidden acts (fp16)

// ---------------- helpers ----------------
__device__ __forceinline__ unsigned smem_u32(const void* p) {
    unsigned a;
    asm("{ .reg .u64 t; cvta.to.shared.u64 t, %1; cvt.u32.u64 %0, t; }" : "=r"(a) : "l"(p));
    return a;
}
// pack two fp32 -> f16x2 (round-to-nearest-even), lo = first arg
__device__ __forceinline__ unsigned pk(float lo, float hi) {
    unsigned r;
    asm("cvt.rn.f16x2.f32 %0, %1, %2;" : "=r"(r) : "f"(hi), "f"(lo));
    return r;
}
__device__ __forceinline__ void sts64(unsigned a, unsigned x, unsigned y) {
    asm volatile("st.shared.v2.b32 [%0], {%1,%2};" :: "r"(a), "r"(x), "r"(y) : "memory");
}
__device__ __forceinline__ void sts128r(unsigned a, unsigned x, unsigned y, unsigned z, unsigned w) {
    asm volatile("st.shared.v4.b32 [%0], {%1,%2,%3,%4};" :: "r"(a), "r"(x), "r"(y), "r"(z), "r"(w) : "memory");
}
__device__ __forceinline__ void ldm_x4(unsigned& r0, unsigned& r1, unsigned& r2, unsigned& r3,
                                       unsigned addr) {
    asm volatile("ldmatrix.sync.aligned.m8n8.x4.shared.b16 {%0,%1,%2,%3}, [%4];"
                 : "=r"(r0), "=r"(r1), "=r"(r2), "=r"(r3) : "r"(addr));
}
__device__ __forceinline__ void mma16816(float* d, const unsigned* a, const unsigned* b) {
    asm volatile("mma.sync.aligned.m16n8k16.row.col.f32.f16.f16.f32 "
                 "{%0,%1,%2,%3}, {%4,%5,%6,%7}, {%8,%9}, {%0,%1,%2,%3};"
                 : "+f"(d[0]), "+f"(d[1]), "+f"(d[2]), "+f"(d[3])
                 : "r"(a[0]), "r"(a[1]), "r"(a[2]), "r"(a[3]), "r"(b[0]), "r"(b[1]));
}
__device__ __forceinline__ void cpa16(unsigned dst, const void* src, int sz) {
    asm volatile("cp.async.cg.shared.global [%0], [%1], 16, %2;"
                 :: "r"(dst), "l"(src), "r"(sz) : "memory");
}
__device__ __forceinline__ void cpa_commit() { asm volatile("cp.async.commit_group;" ::: "memory"); }
__device__ __forceinline__ void cpa_wait0()  { asm volatile("cp.async.wait_group 0;"  ::: "memory"); }

// ---------------- init: zero counts + output ----------------
__global__ void init_kernel(float* __restrict__ out, int n_out) {
    int i = blockIdx.x * blockDim.x + threadIdx.x;
    if (i < NE) g_counts[i] = 0;
    int stride = gridDim.x * blockDim.x;
    for (int j = i; j < n_out; j += stride) out[j] = 0.0f;
}

// ---------------- router (validated) ----------------
__global__ void router_kernel(const float* __restrict__ x,
                              const float* __restrict__ Wr,
                              const float* __restrict__ br) {
    const int t = blockIdx.x;
    const int tid = threadIdx.x;  // 128 threads
    float acc[NE];
#pragma unroll
    for (int e = 0; e < NE; e++) acc[e] = 0.0f;
    const float* xr = x + (size_t)t * D_MODEL;
    for (int d = tid; d < D_MODEL; d += 128) {
        float xv = xr[d];
        const float4* w4 = reinterpret_cast<const float4*>(Wr + (size_t)d * NE);
        float4 a = w4[0], b = w4[1];
        acc[0] += xv * a.x; acc[1] += xv * a.y;
        acc[2] += xv * a.z; acc[3] += xv * a.w;
        acc[4] += xv * b.x; acc[5] += xv * b.y;
        acc[6] += xv * b.z; acc[7] += xv * b.w;
    }
    __shared__ float red[128][NE];
#pragma unroll
    for (int e = 0; e < NE; e++) red[tid][e] = acc[e];
    __syncthreads();
    for (int s = 64; s > 0; s >>= 1) {
        if (tid < s) {
#pragma unroll
            for (int e = 0; e < NE; e++) red[tid][e] += red[tid + s][e];
        }
        __syncthreads();
    }
    if (tid == 0) {
        float l[NE];
#pragma unroll
        for (int e = 0; e < NE; e++) l[e] = red[0][e] + br[e];
        int i0 = 0;
#pragma unroll
        for (int e = 1; e < NE; e++) if (l[e] > l[i0]) i0 = e;
        int i1 = (i0 == 0) ? 1 : 0;
#pragma unroll
        for (int e = 0; e < NE; e++) if (e != i0 && l[e] > l[i1]) i1 = e;
        float m  = fmaxf(l[i0], l[i1]);
        float e0 = expf(l[i0] - m), e1 = expf(l[i1] - m);
        float inv = 1.0f / (e0 + e1);
        int p0 = atomicAdd(&g_counts[i0], 1);
        g_tok[i0 * MAX_T + p0] = t;  g_w[i0 * MAX_T + p0] = e0 * inv;
        int p1 = atomicAdd(&g_counts[i1], 1);
        g_tok[i1 * MAX_T + p1] = t;  g_w[i1 * MAX_T + p1] = e1 * inv;
    }
}

__global__ void offsets_kernel() {
    int off = 0;
#pragma unroll
    for (int e = 0; e < NE; e++) { g_offsets[e] = off; off += g_counts[e]; }
}

// =====================================================================
// GEMM1 (fp16 mma m16n8k16): CTA = 128 tokens x 64 f (gate+up fused; B tile
// 128 rows: [0,64)=gate f, [64,128)=up f). K=1024, BK=32, 8 warps (2m x 4n),
// warp tile 64m x 32n (16 gate + 16 up). 2 CTAs/SM. Single sync per stage.
// =====================================================================
__global__ __launch_bounds__(256, 2) void gemm1_tc(
    const float* __restrict__ x,
    const float* __restrict__ Wg, const float* __restrict__ bg,
    const float* __restrict__ Wu, const float* __restrict__ bu) {
    const int e   = blockIdx.z;
    const int cnt = g_counts[e];
    const int m0  = blockIdx.x * 128;
    if (m0 >= cnt) return;
    const int f0  = blockIdx.y * 64;

    extern __shared__ char dsm[];
    const unsigned sbase = (smem_u32(dsm) + 1023u) & ~1023u;

    const int tid = threadIdx.x, wid = tid >> 5, lane = tid & 31;
    const int wm = wid & 1, wn = wid >> 1;

    // A gather
    const int ar = tid >> 1, ah = tid & 1;
    const float* ap = nullptr;
    if (m0 + ar < cnt) ap = x + (size_t)g_tok[e * MAX_T + m0 + ar] * D_MODEL + ah * 16;
    const float* wgp = Wg + (size_t)e * D_MODEL * D_FF + f0;
    const float* wup = Wu + (size_t)e * D_MODEL * D_FF + f0;
    const int kr = wid * 4;

    float d[4][4][4];
#pragma unroll
    for (int i = 0; i < 4; i++)
#pragma unroll
        for (int j = 0; j < 4; j++)
#pragma unroll
            for (int q = 0; q < 4; q++) d[i][j][q] = 0.f;

    unsigned pa[8], pb[8];

    auto ldg = [&](int k0) {
#pragma unroll
        for (int q = 0; q < 4; q++) {
            float4 v = make_float4(0.f, 0.f, 0.f, 0.f);
            if (ap) v = *reinterpret_cast<const float4*>(ap + k0 + q * 4);
            pa[q * 2] = pk(v.x, v.y); pa[q * 2 + 1] = pk(v.z, v.w);
        }
#pragma unroll
        for (int j = 0; j < 4; j++) {
            const float* wp = (j < 2) ? wgp : wup;
            const float* p = wp + (size_t)(k0 + kr) * D_FF + lane + 32 * (j & 1);
            float w0 = p[0], w1 = p[D_FF], w2 = p[2 * D_FF], w3 = p[3 * D_FF];
            pb[j * 2] = pk(w0, w1); pb[j * 2 + 1] = pk(w2, w3);
        }
    };
    auto sts = [&](int buf) {
        unsigned Ab = sbase + (unsigned)buf * STAGE_BYTES;
        unsigned Bb = Ab + A_BYTES;
        unsigned aa = Ab + (unsigned)(ar * ROWB + ah * 32);
        sts128r(aa,      pa[0], pa[1], pa[2], pa[3]);
        sts128r(aa + 16, pa[4], pa[5], pa[6], pa[7]);
#pragma unroll
        for (int j = 0; j < 4; j++) {
            int row = (j >> 1) * 64 + lane + 32 * (j & 1);
            sts64(Bb + (unsigned)(row * ROWB + kr * 2), pb[j * 2], pb[j * 2 + 1]);
        }
    };
    auto comp = [&](int buf) {
        unsigned Ab = sbase + (unsigned)buf * STAGE_BYTES;
        unsigned Bb = Ab + A_BYTES;
        const int arow = wm * 64 + ((lane >> 3) & 1) * 8 + (lane & 7);
        const int brow = wn * 16 + (lane >> 4) * 8 + (lane & 7);
#pragma unroll
        for (int ks = 0; ks < 2; ks++) {
            unsigned a[4][4];
#pragma unroll
            for (int mf = 0; mf < 4; mf++)
                ldm_x4(a[mf][0], a[mf][1], a[mf][2], a[mf][3],
                       Ab + (unsigned)((arow + mf * 16) * ROWB) +
                       (unsigned)((ks * 2 + (lane >> 4)) * 16));
            unsigned b[4][2];
#pragma unroll
            for (int g = 0; g < 2; g++)
                ldm_x4(b[2 * g][0], b[2 * g][1], b[2 * g + 1][0], b[2 * g + 1][1],
                       Bb + (unsigned)((g * 64 + brow) * ROWB) +
                       (unsigned)((ks * 2 + ((lane >> 3) & 1)) * 16));
#pragma unroll
            for (int mf = 0; mf < 4; mf++)
#pragma unroll
                for (int nf = 0; nf < 4; nf++)
                    mma16816(d[mf][nf], a[mf], b[nf]);
        }
    };

    ldg(0); sts(0); __syncthreads();
    const int NST = D_MODEL / BK;   // 32
    for (int s = 0; s < NST; s++) {
        if (s + 1 < NST) {
            ldg((s + 1) * BK);
            comp(s & 1);
            sts((s + 1) & 1);     // other buffer: freed by previous barrier
            __syncthreads();
        } else {
            comp(s & 1);
        }
    }

    // epilogue: h = silu(g+bg)*(u+bu) -> g_H fp16 (nf<2 gate, nf>=2 up, same f)
    const int hb = g_offsets[e];
    const float* bge = bg + (size_t)e * D_FF;
    const float* bue = bu + (size_t)e * D_FF;
    const int mbase = m0 + wm * 64 + (lane >> 2);
    const int cb = (lane & 3) * 2;
#pragma unroll
    for (int mf = 0; mf < 4; mf++) {
#pragma unroll
        for (int rs = 0; rs < 2; rs++) {
            int gr = mbase + mf * 16 + rs * 8;
            if (gr >= cnt) continue;
            __half* hrow = g_H + (size_t)(hb + gr) * D_FF;
#pragma unroll
            for (int nf = 0; nf < 2; nf++) {
                int f = f0 + wn * 16 + nf * 8 + cb;
                float g0 = d[mf][nf][rs * 2 + 0] + bge[f];
                float g1 = d[mf][nf][rs * 2 + 1] + bge[f + 1];
                float u0 = d[mf][nf + 2][rs * 2 + 0] + bue[f];
                float u1 = d[mf][nf + 2][rs * 2 + 1] + bue[f + 1];
                float h0 = (g0 / (1.0f + expf(-g0))) * u0;
                float h1 = (g1 / (1.0f + expf(-g1))) * u1;
                *reinterpret_cast<__half2*>(hrow + f) = __floats2half2_rn(h0, h1);
            }
        }
    }
}

// =====================================================================
// GEMM2 (fp16): out[tok] += w * (H @ Wd + bd). CTA 128 x 128, K=4096, BK=32.
// A (g_H, already fp16) via cp.async; B (Wd fp32) via ldg+cvt. Warp 64x32.
// =====================================================================
__global__ __launch_bounds__(256, 2) void gemm2_tc(
    const float* __restrict__ Wd, const float* __restrict__ bd,
    float* __restrict__ out) {
    const int e   = blockIdx.z;
    const int cnt = g_counts[e];
    const int m0  = blockIdx.x * 128;
    if (m0 >= cnt) return;
    const int n0  = blockIdx.y * 128;

    extern __shared__ char dsm[];
    const unsigned sbase = (smem_u32(dsm) + 1023u) & ~1023u;

    const int tid = threadIdx.x, wid = tid >> 5, lane = tid & 31;
    const int wm = wid & 1, wn = wid >> 1;

    const int hb = g_offsets[e];
    const int ar = tid >> 1, ah = tid & 1;
    const int arow_ok = (m0 + ar < cnt);
    int hrowi = hb + m0 + ar; if (hrowi > 2 * MAX_T - 1) hrowi = 2 * MAX_T - 1;
    const __half* ap = g_H + (size_t)hrowi * D_FF + ah * 16;
    const int asz = arow_ok ? 16 : 0;
    const float* wdp = Wd + (size_t)e * D_FF * D_MODEL + n0;
    const int kr = wid * 4;

    float d[4][4][4];
#pragma unroll
    for (int i = 0; i < 4; i++)
#pragma unroll
        for (int j = 0; j < 4; j++)
#pragma unroll
            for (int q = 0; q < 4; q++) d[i][j][q] = 0.f;

    unsigned pb[8];

    auto ldg = [&](int k0, int buf) {
        // A: cp.async straight from fp16 g_H (2 x 16B per thread)
        unsigned Ab = sbase + (unsigned)buf * STAGE_BYTES;
        unsigned aa = Ab + (unsigned)(ar * ROWB + ah * 32);
        cpa16(aa,      ap + k0,     asz);
        cpa16(aa + 16, ap + k0 + 8, asz);
        cpa_commit();
        // B: ldg + pack
#pragma unroll
        for (int j = 0; j < 4; j++) {
            const float* p = wdp + (size_t)(k0 + kr) * D_MODEL + lane + 32 * j;
            float w0 = p[0], w1 = p[D_MODEL], w2 = p[2 * D_MODEL], w3 = p[3 * D_MODEL];
            pb[j * 2] = pk(w0, w1); pb[j * 2 + 1] = pk(w2, w3);
        }
    };
    auto sts = [&](int buf) {
        unsigned Bb = sbase + (unsigned)buf * STAGE_BYTES + A_BYTES;
#pragma unroll
        for (int j = 0; j < 4; j++)
            sts64(Bb + (unsigned)((lane + 32 * j) * ROWB + kr * 2), pb[j * 2], pb[j * 2 + 1]);
    };
    auto comp = [&](int buf) {
        unsigned Ab = sbase + (unsigned)buf * STAGE_BYTES;
        unsigned Bb = Ab + A_BYTES;
        const int arow = wm * 64 + ((lane >> 3) & 1) * 8 + (lane & 7);
        const int brow = wn * 32 + (lane >> 4) * 8 + (lane & 7);
#pragma unroll
        for (int ks = 0; ks < 2; ks++) {
            unsigned a[4][4];
#pragma unroll
            for (int mf = 0; mf < 4; mf++)
                ldm_x4(a[mf][0], a[mf][1], a[mf][2], a[mf][3],
                       Ab + (unsigned)((arow + mf * 16) * ROWB) +
                       (unsigned)((ks * 2 + (lane >> 4)) * 16));
            unsigned b[4][2];
#pragma unroll
            for (int g = 0; g < 2; g++)
                ldm_x4(b[2 * g][0], b[2 * g][1], b[2 * g + 1][0], b[2 * g + 1][1],
                       Bb + (unsigned)((brow + g * 16) * ROWB) +
                       (unsigned)((ks * 2 + ((lane >> 3) & 1)) * 16));
#pragma unroll
            for (int mf = 0; mf < 4; mf++)
#pragma unroll
                for (int nf = 0; nf < 4; nf++)
                    mma16816(d[mf][nf], a[mf], b[nf]);
        }
    };

    ldg(0, 0); sts(0); cpa_wait0(); __syncthreads();
    const int NST = D_FF / BK;   // 128
    for (int s = 0; s < NST; s++) {
        if (s + 1 < NST) {
            ldg((s + 1) * BK, (s + 1) & 1);
            comp(s & 1);
            sts((s + 1) & 1);
            cpa_wait0();
            __syncthreads();
        } else {
            comp(s & 1);
        }
    }

    // epilogue: out[tok, n] += w * (acc + bd)
    const float* bde = bd + (size_t)e * D_MODEL;
    const int mbase = m0 + wm * 64 + (lane >> 2);
    const int cb = (lane & 3) * 2;
#pragma unroll
    for (int mf = 0; mf < 4; mf++) {
#pragma unroll
        for (int rs = 0; rs < 2; rs++) {
            int gr = mbase + mf * 16 + rs * 8;
            if (gr >= cnt) continue;
            int   tok = g_tok[e * MAX_T + gr];
            float wgt = g_w[e * MAX_T + gr];
            float* orow = out + (size_t)tok * D_MODEL;
#pragma unroll
            for (int nf = 0; nf < 4; nf++) {
                int n = n0 + wn * 32 + nf * 8 + cb;
                atomicAdd(&orow[n],     wgt * (d[mf][nf][rs * 2 + 0] + bde[n]));
                atomicAdd(&orow[n + 1], wgt * (d[mf][nf][rs * 2 + 1] + bde[n + 1]));
            }
        }
    }
}

// ---------------- launch ----------------
extern "C" void kernel_launch(void* const* d_in, const int* in_sizes, int n_in,
                              void* d_out, int out_size) {
    const float* x  = (const float*)d_in[0];
    const float* Wr = (const float*)d_in[1];
    const float* br = (const float*)d_in[2];
    const float* Wg = (const float*)d_in[3];
    const float* bg = (const float*)d_in[4];
    const float* Wu = (const float*)d_in[5];
    const float* bu = (const float*)d_in[6];
    const float* Wd = (const float*)d_in[7];
    const float* bd = (const float*)d_in[8];
    float* out = (float*)d_out;

    int T = in_sizes[0] / D_MODEL;   // 2048

    const int SMEM = 1024 + 2 * (int)STAGE_BYTES;   // 1024 + 40960
    cudaFuncSetAttribute(gemm1_tc, cudaFuncAttributeMaxDynamicSharedMemorySize, SMEM);
    cudaFuncSetAttribute(gemm2_tc, cudaFuncAttributeMaxDynamicSharedMemorySize, SMEM);

    init_kernel<<<256, 256>>>(out, out_size);
    router_kernel<<<T, 128>>>(x, Wr, br);
    offsets_kernel<<<1, 1>>>();

    dim3 g1(MAX_T / 128, D_FF / 64, NE);      // (16, 64, 8); x fastest -> B reuse in L2
    gemm1_tc<<<g1, 256, SMEM>>>(x, Wg, bg, Wu, bu);

    dim3 g2(MAX_T / 128, D_MODEL / 128, NE);  // (16, 8, 8)
    gemm2_tc<<<g2, 256, SMEM>>>(Wd, bd, out);
}